// round 11
// baseline (speedup 1.0000x reference)
#include <cuda_runtime.h>
#include <cuda_bf16.h>
#include <math.h>
#include <stdint.h>

// Problem constants
#define PB 4
#define PS 2048
#define PD 1024
#define PH 16
#define PDH 64

// ---------------------------------------------------------------------------
// Scratch (device globals — no allocations allowed)
// ---------------------------------------------------------------------------
__device__ float g_cos[PS*32];
__device__ float g_sin[PS*32];

__device__ __nv_bfloat16 g_xh[8192*1024], g_xl[8192*1024];      // x
__device__ __nv_bfloat16 g_wqh[3072*1024], g_wql[3072*1024];    // W_qkv
__device__ __nv_bfloat16 g_woh[1024*1024], g_wol[1024*1024];    // W_o
__device__ __nv_bfloat16 g_ah[8192*1024], g_al[8192*1024];      // attn out
__device__ __nv_bfloat16 gq_h[PB*PH*PS*PDH], gq_l[PB*PH*PS*PDH];
__device__ __nv_bfloat16 gk_h[PB*PH*PS*PDH], gk_l[PB*PH*PS*PDH];
__device__ __nv_bfloat16 gv_h[PB*PH*PS*PDH], gv_l[PB*PH*PS*PDH];

// ---------------------------------------------------------------------------
// Portable PTX helpers
// ---------------------------------------------------------------------------
__device__ __forceinline__ uint32_t smem_u32(const void* p) {
    uint32_t a;
    asm("{ .reg .u64 t; cvta.to.shared.u64 t, %1; cvt.u32.u64 %0, t; }"
        : "=r"(a) : "l"(p));
    return a;
}

__device__ __forceinline__ void cp16(uint32_t saddr, const void* gaddr) {
    asm volatile("cp.async.cg.shared.global [%0], [%1], 16;"
                 :: "r"(saddr), "l"(gaddr) : "memory");
}
#define CP_COMMIT() asm volatile("cp.async.commit_group;" ::: "memory")
#define CP_WAIT0()  asm volatile("cp.async.wait_group 0;" ::: "memory")
#define CP_WAIT1()  asm volatile("cp.async.wait_group 1;" ::: "memory")

__device__ __forceinline__ void ldm_x4(uint32_t* r, uint32_t addr) {
    asm volatile("ldmatrix.sync.aligned.m8n8.x4.shared.b16 {%0,%1,%2,%3}, [%4];"
        : "=r"(r[0]), "=r"(r[1]), "=r"(r[2]), "=r"(r[3]) : "r"(addr));
}
__device__ __forceinline__ void ldm_x4_t(uint32_t* r, uint32_t addr) {
    asm volatile("ldmatrix.sync.aligned.m8n8.x4.trans.shared.b16 {%0,%1,%2,%3}, [%4];"
        : "=r"(r[0]), "=r"(r[1]), "=r"(r[2]), "=r"(r[3]) : "r"(addr));
}

__device__ __forceinline__ void mma16816(float* d, const uint32_t* a, const uint32_t* b) {
    asm volatile(
        "mma.sync.aligned.m16n8k16.row.col.f32.bf16.bf16.f32 "
        "{%0,%1,%2,%3}, {%4,%5,%6,%7}, {%8,%9}, {%0,%1,%2,%3};"
        : "+f"(d[0]), "+f"(d[1]), "+f"(d[2]), "+f"(d[3])
        : "r"(a[0]), "r"(a[1]), "r"(a[2]), "r"(a[3]), "r"(b[0]), "r"(b[1]));
}

__device__ __forceinline__ uint32_t bpack(float a, float b) {
    unsigned short la = __bfloat16_as_ushort(__float2bfloat16(a));
    unsigned short lb = __bfloat16_as_ushort(__float2bfloat16(b));
    return (uint32_t)la | ((uint32_t)lb << 16);
}
__device__ __forceinline__ float bhi(float a) {
    return __bfloat162float(__float2bfloat16(a));
}

// Fast exp on FMA pipe (valid for x <= ~0, clamps at -87)
__device__ __forceinline__ float fexp(float x) {
    float xc = fmaxf(x, -87.0f);
    float t  = fmaf(xc, 1.4426950408889634f, 12582912.0f);
    float n  = t - 12582912.0f;
    float r  = fmaf(n, -0.6931471805599453f, xc);
    float p  = 8.3333333e-3f;
    p = fmaf(p, r, 4.1666667e-2f);
    p = fmaf(p, r, 1.6666667e-1f);
    p = fmaf(p, r, 5.0e-1f);
    p = fmaf(p, r, 1.0f);
    p = fmaf(p, r, 1.0f);
    float s = __int_as_float((__float_as_int(t) << 23) + 0x3f800000);
    return p * s;
}

// ---------------------------------------------------------------------------
// RoPE table (fp64 for fidelity)
// ---------------------------------------------------------------------------
__global__ void rope_table_kernel(const int* __restrict__ pos) {
    int idx = blockIdx.x * blockDim.x + threadIdx.x;   // 65536
    int s = idx >> 5;
    int i = idx & 31;
    double p = (double)pos[s];
    double inv = exp(-((double)(2 * i) / 64.0) * log(10000.0));
    double a = p * inv;
    g_cos[idx] = (float)cos(a);
    g_sin[idx] = (float)sin(a);
}

// ---------------------------------------------------------------------------
// fp32 -> bf16 hi/lo split
// ---------------------------------------------------------------------------
__device__ __forceinline__ void split4(const float* __restrict__ src,
                                       __nv_bfloat16* __restrict__ hi,
                                       __nv_bfloat16* __restrict__ lo) {
    int i = blockIdx.x * blockDim.x + threadIdx.x;
    float4 v = ((const float4*)src)[i];
    ((uint32_t*)hi)[i*2]   = bpack(v.x, v.y);
    ((uint32_t*)hi)[i*2+1] = bpack(v.z, v.w);
    ((uint32_t*)lo)[i*2]   = bpack(v.x - bhi(v.x), v.y - bhi(v.y));
    ((uint32_t*)lo)[i*2+1] = bpack(v.z - bhi(v.z), v.w - bhi(v.w));
}

__global__ void split_x_kernel(const float* __restrict__ x)  { split4(x, g_xh, g_xl); }
__global__ void split_wq_kernel(const float* __restrict__ w) { split4(w, g_wqh, g_wql); }
__global__ void split_wo_kernel(const float* __restrict__ w) { split4(w, g_woh, g_wol); }

// ---------------------------------------------------------------------------
// mma.sync bf16 GEMM v2: 128x128 CTA tile, BK=32, 128 threads (4 warps),
// warp tile 64x64 (2x2 warp grid) -> 16 ldmatrix feed 96 MMAs per k16.
// 2-stage cp.async pipeline. 3-term split: AhBh + AhBl + AlBh, fp32 acc.
// MODE 0: A=x, B=W_qkv, epilogue RoPE + bf16-split scatter into gq/gk/gv.
// MODE 1: A=attn(bf16 split), B=W_o, epilogue fp32 store into Cout.
// ---------------------------------------------------------------------------
#define LDT 40
#define TILE_B (128*LDT*2)        // 10240 B
#define STAGE_B (4*TILE_B)        // 40960 B
#define GEMM_SMEM (2*STAGE_B)     // 81920 B

template<int MODE>
__global__ __launch_bounds__(128, 2)
void mma_gemm_kernel(float* __restrict__ Cout)
{
    const __nv_bfloat16 *Ahp, *Alp, *Bhp, *Blp;
    if (MODE == 0) { Ahp = g_xh; Alp = g_xl; Bhp = g_wqh; Blp = g_wql; }
    else           { Ahp = g_ah; Alp = g_al; Bhp = g_woh; Blp = g_wol; }

    extern __shared__ char dsm[];
    const uint32_t sBase = smem_u32(dsm);

    const int tid = threadIdx.x;
    const int n0 = blockIdx.x * 128;
    const int m0 = blockIdx.y * 128;
    const int lane = tid & 31, w = tid >> 5;
    const int wm = w >> 1, wn = w & 1;

    // gmem -> smem: thread tid covers row tid (128 rows), all 32 cols (64 B)
    const __nv_bfloat16* gAh = Ahp + (size_t)(m0 + tid) * 1024;
    const __nv_bfloat16* gAl = Alp + (size_t)(m0 + tid) * 1024;
    const __nv_bfloat16* gBh = Bhp + (size_t)(n0 + tid) * 1024;
    const __nv_bfloat16* gBl = Blp + (size_t)(n0 + tid) * 1024;
    const uint32_t sOff = (uint32_t)(tid * (LDT*2));

    const int quad = lane >> 3, qi = lane & 7;
    const uint32_t aoff = (uint32_t)(((wm*64 + (quad&1)*8 + qi) * LDT + (quad>>1)*8) * 2);
    const uint32_t boff = (uint32_t)(((wn*64 + (quad>>1)*8 + qi) * LDT + (quad&1)*8) * 2);

    float acc[4][8][4];
#pragma unroll
    for (int a = 0; a < 4; a++)
#pragma unroll
        for (int b = 0; b < 8; b++)
#pragma unroll
            for (int c = 0; c < 4; c++) acc[a][b][c] = 0.0f;

    auto load_stage = [&](int kt, int stg) {
        const int kb = kt * 32;
        const uint32_t s0 = sBase + stg * STAGE_B + sOff;
#pragma unroll
        for (int u = 0; u < 4; u++) {
            cp16(s0 + u*16,            (const char*)(gAh + kb) + u*16);
            cp16(s0 + TILE_B + u*16,   (const char*)(gAl + kb) + u*16);
            cp16(s0 + 2*TILE_B + u*16, (const char*)(gBh + kb) + u*16);
            cp16(s0 + 3*TILE_B + u*16, (const char*)(gBl + kb) + u*16);
        }
        CP_COMMIT();
    };

    load_stage(0, 0);

    for (int kt = 0; kt < 32; kt++) {
        const int stg = kt & 1;
        if (kt + 1 < 32) { load_stage(kt + 1, stg ^ 1); CP_WAIT1(); }
        else CP_WAIT0();
        __syncthreads();

        const uint32_t sAhB = sBase + stg * STAGE_B;
        const uint32_t sAlB = sAhB + TILE_B;
        const uint32_t sBhB = sAhB + 2*TILE_B;
        const uint32_t sBlB = sAhB + 3*TILE_B;

#pragma unroll
        for (int ks = 0; ks < 2; ks++) {
            const uint32_t kso = ks * 32;
            uint32_t aH[4][4], aL[4][4], bH[4][4], bL[4][4];
#pragma unroll
            for (int mt = 0; mt < 4; mt++) {
                ldm_x4(aH[mt], sAhB + aoff + mt * (16*LDT*2) + kso);
                ldm_x4(aL[mt], sAlB + aoff + mt * (16*LDT*2) + kso);
            }
#pragma unroll
            for (int np = 0; np < 4; np++) {
                ldm_x4(bH[np], sBhB + boff + np * (16*LDT*2) + kso);
                ldm_x4(bL[np], sBlB + boff + np * (16*LDT*2) + kso);
            }
#pragma unroll
            for (int mt = 0; mt < 4; mt++)
#pragma unroll
                for (int nt = 0; nt < 8; nt++) {
                    const uint32_t* ph = &bH[nt >> 1][(nt & 1) * 2];
                    const uint32_t* pl = &bL[nt >> 1][(nt & 1) * 2];
                    mma16816(acc[mt][nt], aH[mt], ph);
                    mma16816(acc[mt][nt], aH[mt], pl);
                    mma16816(acc[mt][nt], aL[mt], ph);
                }
        }
        __syncthreads();
    }

    const int g = lane >> 2, tig = lane & 3;
    if (MODE == 0) {
        const int kmat = n0 >> 10;                   // 0=q 1=k 2=v
        __nv_bfloat16* dH = (kmat == 0) ? gq_h : ((kmat == 1) ? gk_h : gv_h);
        __nv_bfloat16* dL = (kmat == 0) ? gq_l : ((kmat == 1) ? gk_l : gv_l);
#pragma unroll
        for (int mt = 0; mt < 4; mt++)
#pragma unroll
            for (int hh = 0; hh < 2; hh++) {
                const int m = m0 + wm*64 + mt*16 + hh*8 + g;
                const int b = m >> 11, s = m & 2047;
#pragma unroll
                for (int nt = 0; nt < 8; nt++) {
                    const int colg = n0 + wn*64 + nt*8 + 2*tig;
                    const int h = (colg >> 6) & 15;
                    const int cc = colg & 63;
                    const float v0 = acc[mt][nt][hh*2];
                    const float v1 = acc[mt][nt][hh*2 + 1];
                    float rx, ry;
                    if (kmat < 2) {
                        const int pi = (s << 5) + (cc >> 1);
                        const float c_ = g_cos[pi], s_ = g_sin[pi];
                        rx = v0 * c_ - v1 * s_;
                        ry = v0 * s_ + v1 * c_;
                    } else {
                        rx = v0; ry = v1;
                    }
                    size_t idx = ((size_t)((b*PH + h)*PS + s))*PDH + cc;
                    *(uint32_t*)(dH + idx) = bpack(rx, ry);
                    *(uint32_t*)(dL + idx) = bpack(rx - bhi(rx), ry - bhi(ry));
                }
            }
    } else {
#pragma unroll
        for (int mt = 0; mt < 4; mt++)
#pragma unroll
            for (int hh = 0; hh < 2; hh++) {
                const int m = m0 + wm*64 + mt*16 + hh*8 + g;
#pragma unroll
                for (int nt = 0; nt < 8; nt++) {
                    const int colg = n0 + wn*64 + nt*8 + 2*tig;
                    float2 r;
                    r.x = acc[mt][nt][hh*2];
                    r.y = acc[mt][nt][hh*2 + 1];
                    *(float2*)(Cout + (size_t)m * 1024 + colg) = r;
                }
            }
    }
}

// ---------------------------------------------------------------------------
// Tensor-core flash attention (unchanged from R10 WIN).
// ---------------------------------------------------------------------------
#define FTILE 9216            // 64 rows * 144 B (72-bf16 stride)
#define FSTG  (4*FTILE)
#define FLASH_SMEM (2*FSTG)   // 73728

__global__ __launch_bounds__(256) void flash_mma_kernel() {
    extern __shared__ char fsm[];
    const uint32_t sb = smem_u32(fsm);
    const int tid = threadIdx.x, lane = tid & 31, w = tid >> 5;
    const int qb = 15 - (int)blockIdx.x;
    const int bh = blockIdx.y;
    const int quad = lane >> 3, qi = lane & 7;
    const int g = lane >> 2, tig = lane & 3;

    const size_t bhoff = (size_t)bh * PS * PDH;
    const __nv_bfloat16* Kh0 = gk_h + bhoff;
    const __nv_bfloat16* Kl0 = gk_l + bhoff;
    const __nv_bfloat16* Vh0 = gv_h + bhoff;
    const __nv_bfloat16* Vl0 = gv_l + bhoff;

    {
        const int r = tid & 127;
        const __nv_bfloat16* src = (tid < 128 ? gq_h : gq_l) + bhoff + (size_t)(qb*128 + r)*PDH;
        uint32_t dst = sb + (tid < 128 ? 0u : 18432u) + (uint32_t)r*144;
#pragma unroll
        for (int u = 0; u < 8; u++) cp16(dst + u*16, (const char*)src + u*16);
        CP_COMMIT();
    }
    CP_WAIT0();
    __syncthreads();

    uint32_t qH[4][4], qL[4][4];
    {
        const uint32_t ao = (uint32_t)((w*16 + (quad&1)*8 + qi)*144 + (quad>>1)*16);
#pragma unroll
        for (int kd = 0; kd < 4; kd++) {
            ldm_x4(qH[kd], sb + ao + kd*32);
            ldm_x4(qL[kd], sb + 18432 + ao + kd*32);
        }
    }
    __syncthreads();

    const int jmax = 2*qb + 1;

    auto load_kv = [&](int j, int stg) {
        const int t = tid >> 6;
        const int r = tid & 63;
        const __nv_bfloat16* src =
            (t == 0 ? Kh0 : t == 1 ? Kl0 : t == 2 ? Vh0 : Vl0) + (size_t)(j*64 + r)*PDH;
        uint32_t dst = sb + stg*FSTG + t*FTILE + (uint32_t)r*144;
#pragma unroll
        for (int u = 0; u < 8; u++) cp16(dst + u*16, (const char*)src + u*16);
        CP_COMMIT();
    };

    float o[8][4];
#pragma unroll
    for (int t = 0; t < 8; t++) { o[t][0]=0.f; o[t][1]=0.f; o[t][2]=0.f; o[t][3]=0.f; }
    float m0 = -1e30f, m1 = -1e30f, l0 = 0.f, l1 = 0.f;
    const int row0 = qb*128 + w*16 + g;

    load_kv(0, 0);

    for (int j = 0; j <= jmax; j++) {
        const int stg = j & 1;
        if (j < jmax) { load_kv(j + 1, stg ^ 1); CP_WAIT1(); }
        else CP_WAIT0();
        __syncthreads();

        const uint32_t KhB = sb + stg*FSTG;
        const uint32_t KlB = KhB + FTILE;
        const uint32_t VhB = KhB + 2*FTILE;
        const uint32_t VlB = KhB + 3*FTILE;

        float sc[8][4];
#pragma unroll
        for (int t = 0; t < 8; t++) { sc[t][0]=0.f; sc[t][1]=0.f; sc[t][2]=0.f; sc[t][3]=0.f; }

        const uint32_t bo = (uint32_t)(((quad>>1)*8 + qi)*144 + (quad&1)*16);
#pragma unroll
        for (int kd = 0; kd < 4; kd++) {
            uint32_t bKh[4][4], bKl[4][4];
#pragma unroll
            for (int p = 0; p < 4; p++) {
                ldm_x4(bKh[p], KhB + bo + p*(16*144) + kd*32);
                ldm_x4(bKl[p], KlB + bo + p*(16*144) + kd*32);
            }
#pragma unroll
            for (int t = 0; t < 8; t++) {
                const uint32_t* ph = &bKh[t>>1][(t&1)*2];
                const uint32_t* pl = &bKl[t>>1][(t&1)*2];
                mma16816(sc[t], qH[kd], ph);
                mma16816(sc[t], qH[kd], pl);
                mma16816(sc[t], qL[kd], ph);
            }
        }

        if (j*64 + 63 > qb*128 + w*16) {
#pragma unroll
            for (int t = 0; t < 8; t++) {
                const int colb = j*64 + t*8 + 2*tig;
#pragma unroll
                for (int e = 0; e < 4; e++) {
                    const int col = colb + (e & 1);
                    const int row = row0 + ((e >= 2) ? 8 : 0);
                    sc[t][e] = (col > row) ? -1e30f : sc[t][e] * 0.125f;
                }
            }
        } else {
#pragma unroll
            for (int t = 0; t < 8; t++) {
                sc[t][0] *= 0.125f; sc[t][1] *= 0.125f;
                sc[t][2] *= 0.125f; sc[t][3] *= 0.125f;
            }
        }

        float rm0 = -1e30f, rm1 = -1e30f;
#pragma unroll
        for (int t = 0; t < 8; t++) {
            rm0 = fmaxf(rm0, fmaxf(sc[t][0], sc[t][1]));
            rm1 = fmaxf(rm1, fmaxf(sc[t][2], sc[t][3]));
        }
        rm0 = fmaxf(rm0, __shfl_xor_sync(0xffffffffu, rm0, 1));
        rm0 = fmaxf(rm0, __shfl_xor_sync(0xffffffffu, rm0, 2));
        rm1 = fmaxf(rm1, __shfl_xor_sync(0xffffffffu, rm1, 1));
        rm1 = fmaxf(rm1, __shfl_xor_sync(0xffffffffu, rm1, 2));
        const float mn0 = fmaxf(m0, rm0), mn1 = fmaxf(m1, rm1);
        const float a0 = fexp(m0 - mn0), a1 = fexp(m1 - mn1);
        float s0 = 0.f, s1 = 0.f;
#pragma unroll
        for (int t = 0; t < 8; t++) {
            sc[t][0] = fexp(sc[t][0] - mn0); sc[t][1] = fexp(sc[t][1] - mn0);
            sc[t][2] = fexp(sc[t][2] - mn1); sc[t][3] = fexp(sc[t][3] - mn1);
            s0 += sc[t][0] + sc[t][1];
            s1 += sc[t][2] + sc[t][3];
        }
        s0 += __shfl_xor_sync(0xffffffffu, s0, 1);
        s0 += __shfl_xor_sync(0xffffffffu, s0, 2);
        s1 += __shfl_xor_sync(0xffffffffu, s1, 1);
        s1 += __shfl_xor_sync(0xffffffffu, s1, 2);
        l0 = l0 * a0 + s0; l1 = l1 * a1 + s1;
        m0 = mn0; m1 = mn1;
#pragma unroll
        for (int t = 0; t < 8; t++) {
            o[t][0] *= a0; o[t][1] *= a0; o[t][2] *= a1; o[t][3] *= a1;
        }

        const uint32_t vo = (uint32_t)(((quad&1)*8 + qi)*144 + (quad>>1)*16);
#pragma unroll
        for (int kk = 0; kk < 4; kk++) {
            const int t0 = 2*kk, t1 = 2*kk + 1;
            uint32_t aph[4], apl[4];
            aph[0] = bpack(sc[t0][0], sc[t0][1]);
            aph[1] = bpack(sc[t0][2], sc[t0][3]);
            aph[2] = bpack(sc[t1][0], sc[t1][1]);
            aph[3] = bpack(sc[t1][2], sc[t1][3]);
            apl[0] = bpack(sc[t0][0]-bhi(sc[t0][0]), sc[t0][1]-bhi(sc[t0][1]));
            apl[1] = bpack(sc[t0][2]-bhi(sc[t0][2]), sc[t0][3]-bhi(sc[t0][3]));
            apl[2] = bpack(sc[t1][0]-bhi(sc[t1][0]), sc[t1][1]-bhi(sc[t1][1]));
            apl[3] = bpack(sc[t1][2]-bhi(sc[t1][2]), sc[t1][3]-bhi(sc[t1][3]));

            uint32_t bVh[4][4], bVl[4][4];
#pragma unroll
            for (int dp = 0; dp < 4; dp++) {
                ldm_x4_t(bVh[dp], VhB + vo + kk*(16*144) + dp*32);
                ldm_x4_t(bVl[dp], VlB + vo + kk*(16*144) + dp*32);
            }
#pragma unroll
            for (int dt = 0; dt < 8; dt++) {
                const uint32_t* ph = &bVh[dt>>1][(dt&1)*2];
                const uint32_t* pl = &bVl[dt>>1][(dt&1)*2];
                mma16816(o[dt], aph, ph);
                mma16816(o[dt], apl, ph);
                mma16816(o[dt], aph, pl);
            }
        }
        __syncthreads();
    }

    const float inv0 = 1.0f / l0, inv1 = 1.0f / l1;
    const int b = bh >> 4, h = bh & 15;
    const int s0r = qb*128 + w*16 + g;
    const int s1r = s0r + 8;
#pragma unroll
    for (int t = 0; t < 8; t++) {
        const float x0 = o[t][0]*inv0, x1 = o[t][1]*inv0;
        const float y0 = o[t][2]*inv1, y1 = o[t][3]*inv1;
        const int col = h*64 + t*8 + 2*tig;
        const size_t i0 = ((size_t)(b*PS + s0r))*PD + col;
        const size_t i1 = ((size_t)(b*PS + s1r))*PD + col;
        *(uint32_t*)(g_ah + i0) = bpack(x0, x1);
        *(uint32_t*)(g_al + i0) = bpack(x0 - bhi(x0), x1 - bhi(x1));
        *(uint32_t*)(g_ah + i1) = bpack(y0, y1);
        *(uint32_t*)(g_al + i1) = bpack(y0 - bhi(y0), y1 - bhi(y1));
    }
}

// ---------------------------------------------------------------------------
extern "C" void kernel_launch(void* const* d_in, const int* in_sizes, int n_in,
                              void* d_out, int out_size) {
    const float* x     = (const float*)d_in[0];
    const float* W_qkv = (const float*)d_in[1];
    const float* W_o   = (const float*)d_in[2];
    const int*   tpos  = (const int*)d_in[3];
    float* out = (float*)d_out;

    cudaFuncSetAttribute(flash_mma_kernel,
                         cudaFuncAttributeMaxDynamicSharedMemorySize, FLASH_SMEM);
    cudaFuncSetAttribute(mma_gemm_kernel<0>,
                         cudaFuncAttributeMaxDynamicSharedMemorySize, GEMM_SMEM);
    cudaFuncSetAttribute(mma_gemm_kernel<1>,
                         cudaFuncAttributeMaxDynamicSharedMemorySize, GEMM_SMEM);

    rope_table_kernel<<<64, 1024>>>(tpos);
    split_x_kernel<<<8192, 256>>>(x);
    split_wq_kernel<<<3072, 256>>>(W_qkv);
    split_wo_kernel<<<1024, 256>>>(W_o);

    mma_gemm_kernel<0><<<dim3(24, 64), 128, GEMM_SMEM>>>(nullptr);   // QKV + RoPE + splits
    flash_mma_kernel<<<dim3(16, 64), 256, FLASH_SMEM>>>();
    mma_gemm_kernel<1><<<dim3(8, 64), 128, GEMM_SMEM>>>(out);        // out proj
}

// round 12
// speedup vs baseline: 1.3433x; 1.3433x over previous
#include <cuda_runtime.h>
#include <cuda_bf16.h>
#include <cuda_fp16.h>
#include <math.h>
#include <stdint.h>

// Problem constants
#define PB 4
#define PS 2048
#define PD 1024
#define PH 16
#define PDH 64

// ---------------------------------------------------------------------------
// Scratch (device globals — no allocations allowed)
// ---------------------------------------------------------------------------
__device__ float g_cos[PS*32];
__device__ float g_sin[PS*32];

// fp16 operands for projection GEMMs (activation hi/lo split, weight single)
__device__ __half g_xh16[8192*1024], g_xl16[8192*1024];
__device__ __half g_wq16[3072*1024];
__device__ __half g_wo16[1024*1024];
__device__ __half g_ah16[8192*1024], g_al16[8192*1024];   // attn out (flash epilogue)

// q/k/v bf16 hi/lo splits for flash (3-term path), layout [b*H+h][s][dh]
__device__ __nv_bfloat16 gq_h[PB*PH*PS*PDH], gq_l[PB*PH*PS*PDH];
__device__ __nv_bfloat16 gk_h[PB*PH*PS*PDH], gk_l[PB*PH*PS*PDH];
__device__ __nv_bfloat16 gv_h[PB*PH*PS*PDH], gv_l[PB*PH*PS*PDH];

// ---------------------------------------------------------------------------
// Portable PTX helpers
// ---------------------------------------------------------------------------
__device__ __forceinline__ uint32_t smem_u32(const void* p) {
    uint32_t a;
    asm("{ .reg .u64 t; cvta.to.shared.u64 t, %1; cvt.u32.u64 %0, t; }"
        : "=r"(a) : "l"(p));
    return a;
}

__device__ __forceinline__ void cp16(uint32_t saddr, const void* gaddr) {
    asm volatile("cp.async.cg.shared.global [%0], [%1], 16;"
                 :: "r"(saddr), "l"(gaddr) : "memory");
}
#define CP_COMMIT() asm volatile("cp.async.commit_group;" ::: "memory")
#define CP_WAIT0()  asm volatile("cp.async.wait_group 0;" ::: "memory")
#define CP_WAIT1()  asm volatile("cp.async.wait_group 1;" ::: "memory")

__device__ __forceinline__ void ldm_x4(uint32_t* r, uint32_t addr) {
    asm volatile("ldmatrix.sync.aligned.m8n8.x4.shared.b16 {%0,%1,%2,%3}, [%4];"
        : "=r"(r[0]), "=r"(r[1]), "=r"(r[2]), "=r"(r[3]) : "r"(addr));
}
__device__ __forceinline__ void ldm_x4_t(uint32_t* r, uint32_t addr) {
    asm volatile("ldmatrix.sync.aligned.m8n8.x4.trans.shared.b16 {%0,%1,%2,%3}, [%4];"
        : "=r"(r[0]), "=r"(r[1]), "=r"(r[2]), "=r"(r[3]) : "r"(addr));
}

// bf16 inputs, f32 acc
__device__ __forceinline__ void mma16816(float* d, const uint32_t* a, const uint32_t* b) {
    asm volatile(
        "mma.sync.aligned.m16n8k16.row.col.f32.bf16.bf16.f32 "
        "{%0,%1,%2,%3}, {%4,%5,%6,%7}, {%8,%9}, {%0,%1,%2,%3};"
        : "+f"(d[0]), "+f"(d[1]), "+f"(d[2]), "+f"(d[3])
        : "r"(a[0]), "r"(a[1]), "r"(a[2]), "r"(a[3]), "r"(b[0]), "r"(b[1]));
}
// fp16 inputs, f32 acc
__device__ __forceinline__ void mma16816h(float* d, const uint32_t* a, const uint32_t* b) {
    asm volatile(
        "mma.sync.aligned.m16n8k16.row.col.f32.f16.f16.f32 "
        "{%0,%1,%2,%3}, {%4,%5,%6,%7}, {%8,%9}, {%0,%1,%2,%3};"
        : "+f"(d[0]), "+f"(d[1]), "+f"(d[2]), "+f"(d[3])
        : "r"(a[0]), "r"(a[1]), "r"(a[2]), "r"(a[3]), "r"(b[0]), "r"(b[1]));
}

__device__ __forceinline__ uint32_t bpack(float a, float b) {
    unsigned short la = __bfloat16_as_ushort(__float2bfloat16(a));
    unsigned short lb = __bfloat16_as_ushort(__float2bfloat16(b));
    return (uint32_t)la | ((uint32_t)lb << 16);
}
__device__ __forceinline__ float bhi(float a) {
    return __bfloat162float(__float2bfloat16(a));
}
__device__ __forceinline__ uint32_t hpack(float a, float b) {
    __half2 h = __floats2half2_rn(a, b);
    return *(uint32_t*)&h;
}
__device__ __forceinline__ float hval(float a) {
    return __half2float(__float2half_rn(a));
}

// Fast exp on FMA pipe (valid for x <= ~0, clamps at -87)
__device__ __forceinline__ float fexp(float x) {
    float xc = fmaxf(x, -87.0f);
    float t  = fmaf(xc, 1.4426950408889634f, 12582912.0f);
    float n  = t - 12582912.0f;
    float r  = fmaf(n, -0.6931471805599453f, xc);
    float p  = 8.3333333e-3f;
    p = fmaf(p, r, 4.1666667e-2f);
    p = fmaf(p, r, 1.6666667e-1f);
    p = fmaf(p, r, 5.0e-1f);
    p = fmaf(p, r, 1.0f);
    p = fmaf(p, r, 1.0f);
    float s = __int_as_float((__float_as_int(t) << 23) + 0x3f800000);
    return p * s;
}

// ---------------------------------------------------------------------------
// RoPE table (fp64 for fidelity)
// ---------------------------------------------------------------------------
__global__ void rope_table_kernel(const int* __restrict__ pos) {
    int idx = blockIdx.x * blockDim.x + threadIdx.x;   // 65536
    int s = idx >> 5;
    int i = idx & 31;
    double p = (double)pos[s];
    double inv = exp(-((double)(2 * i) / 64.0) * log(10000.0));
    double a = p * inv;
    g_cos[idx] = (float)cos(a);
    g_sin[idx] = (float)sin(a);
}

// ---------------------------------------------------------------------------
// Conversions
// ---------------------------------------------------------------------------
__global__ void split_x_kernel(const float* __restrict__ x) {
    int i = blockIdx.x * blockDim.x + threadIdx.x;
    float4 v = ((const float4*)x)[i];
    ((uint32_t*)g_xh16)[i*2]   = hpack(v.x, v.y);
    ((uint32_t*)g_xh16)[i*2+1] = hpack(v.z, v.w);
    ((uint32_t*)g_xl16)[i*2]   = hpack(v.x - hval(v.x), v.y - hval(v.y));
    ((uint32_t*)g_xl16)[i*2+1] = hpack(v.z - hval(v.z), v.w - hval(v.w));
}
__global__ void cvt_wq_kernel(const float* __restrict__ w) {
    int i = blockIdx.x * blockDim.x + threadIdx.x;
    float4 v = ((const float4*)w)[i];
    ((uint32_t*)g_wq16)[i*2]   = hpack(v.x, v.y);
    ((uint32_t*)g_wq16)[i*2+1] = hpack(v.z, v.w);
}
__global__ void cvt_wo_kernel(const float* __restrict__ w) {
    int i = blockIdx.x * blockDim.x + threadIdx.x;
    float4 v = ((const float4*)w)[i];
    ((uint32_t*)g_wo16)[i*2]   = hpack(v.x, v.y);
    ((uint32_t*)g_wo16)[i*2+1] = hpack(v.z, v.w);
}

// ---------------------------------------------------------------------------
// fp16 mma GEMM: 128x128 CTA tile, BK=32, 256 threads, warp tile 64x32,
// 2-stage cp.async pipeline. 2-term: Ah*B + Al*B (A split, B single fp16).
// MODE 0: A=x, B=W_qkv, epilogue RoPE + bf16-split scatter into gq/gk/gv.
// MODE 1: A=attn (fp16 split), B=W_o, epilogue fp32 store into Cout.
// ---------------------------------------------------------------------------
#define LDT 40
#define TILE_B (128*LDT*2)        // 10240 B
#define STAGE_B (3*TILE_B)        // Ah, Al, B = 30720 B
#define GEMM_SMEM (2*STAGE_B)     // 61440 B

template<int MODE>
__global__ __launch_bounds__(256)
void mma_gemm_kernel(float* __restrict__ Cout)
{
    const __half *Ahp, *Alp, *Bp;
    if (MODE == 0) { Ahp = g_xh16; Alp = g_xl16; Bp = g_wq16; }
    else           { Ahp = g_ah16; Alp = g_al16; Bp = g_wo16; }

    extern __shared__ char dsm[];
    const uint32_t sBase = smem_u32(dsm);

    const int tid = threadIdx.x;
    const int n0 = blockIdx.x * 128;
    const int m0 = blockIdx.y * 128;
    const int lane = tid & 31, w = tid >> 5;
    const int wm = w >> 2, wn = w & 3;

    const int lr = tid >> 1, lh = tid & 1;
    const __half* gAh = Ahp + (size_t)(m0 + lr) * 1024 + lh * 16;
    const __half* gAl = Alp + (size_t)(m0 + lr) * 1024 + lh * 16;
    const __half* gB  = Bp  + (size_t)(n0 + lr) * 1024 + lh * 16;
    const uint32_t sOff = (uint32_t)((lr * LDT + lh * 16) * 2);

    const int quad = lane >> 3, qi = lane & 7;
    const uint32_t aoff = (uint32_t)(((wm*64 + (quad&1)*8 + qi) * LDT + (quad>>1)*8) * 2);
    const uint32_t boff = (uint32_t)(((wn*32 + (quad>>1)*8 + qi) * LDT + (quad&1)*8) * 2);

    float acc[4][4][4];
#pragma unroll
    for (int a = 0; a < 4; a++)
#pragma unroll
        for (int b = 0; b < 4; b++)
#pragma unroll
            for (int c = 0; c < 4; c++) acc[a][b][c] = 0.0f;

    auto load_stage = [&](int kt, int stg) {
        const int kb = kt * 32;
        const uint32_t s0 = sBase + stg * STAGE_B + sOff;
        cp16(s0,                gAh + kb);  cp16(s0 + 16,            gAh + kb + 8);
        cp16(s0 + TILE_B,       gAl + kb);  cp16(s0 + TILE_B + 16,   gAl + kb + 8);
        cp16(s0 + 2*TILE_B,     gB  + kb);  cp16(s0 + 2*TILE_B + 16, gB  + kb + 8);
        CP_COMMIT();
    };

    load_stage(0, 0);

    for (int kt = 0; kt < 32; kt++) {
        const int stg = kt & 1;
        if (kt + 1 < 32) { load_stage(kt + 1, stg ^ 1); CP_WAIT1(); }
        else CP_WAIT0();
        __syncthreads();

        const uint32_t sAhB = sBase + stg * STAGE_B;
        const uint32_t sAlB = sAhB + TILE_B;
        const uint32_t sBB  = sAhB + 2*TILE_B;

#pragma unroll
        for (int ks = 0; ks < 2; ks++) {
            const uint32_t kso = ks * 32;
            uint32_t aH[4][4], aL[4][4], bB[2][4];
#pragma unroll
            for (int mt = 0; mt < 4; mt++) {
                ldm_x4(aH[mt], sAhB + aoff + mt * (16*LDT*2) + kso);
                ldm_x4(aL[mt], sAlB + aoff + mt * (16*LDT*2) + kso);
            }
#pragma unroll
            for (int np = 0; np < 2; np++)
                ldm_x4(bB[np], sBB + boff + np * (16*LDT*2) + kso);
#pragma unroll
            for (int mt = 0; mt < 4; mt++)
#pragma unroll
                for (int nt = 0; nt < 4; nt++) {
                    const uint32_t* pb = &bB[nt >> 1][(nt & 1) * 2];
                    mma16816h(acc[mt][nt], aH[mt], pb);
                    mma16816h(acc[mt][nt], aL[mt], pb);
                }
        }
        __syncthreads();
    }

    const int g = lane >> 2, tig = lane & 3;
    if (MODE == 0) {
        const int kmat = n0 >> 10;                   // 0=q 1=k 2=v
        __nv_bfloat16* dH = (kmat == 0) ? gq_h : ((kmat == 1) ? gk_h : gv_h);
        __nv_bfloat16* dL = (kmat == 0) ? gq_l : ((kmat == 1) ? gk_l : gv_l);
#pragma unroll
        for (int mt = 0; mt < 4; mt++)
#pragma unroll
            for (int hh = 0; hh < 2; hh++) {
                const int m = m0 + wm*64 + mt*16 + hh*8 + g;
                const int b = m >> 11, s = m & 2047;
#pragma unroll
                for (int nt = 0; nt < 4; nt++) {
                    const int colg = n0 + wn*32 + nt*8 + 2*tig;
                    const int h = (colg >> 6) & 15;
                    const int cc = colg & 63;
                    const float v0 = acc[mt][nt][hh*2];
                    const float v1 = acc[mt][nt][hh*2 + 1];
                    float rx, ry;
                    if (kmat < 2) {
                        const int pi = (s << 5) + (cc >> 1);
                        const float c_ = g_cos[pi], s_ = g_sin[pi];
                        rx = v0 * c_ - v1 * s_;
                        ry = v0 * s_ + v1 * c_;
                    } else {
                        rx = v0; ry = v1;
                    }
                    size_t idx = ((size_t)((b*PH + h)*PS + s))*PDH + cc;
                    *(uint32_t*)(dH + idx) = bpack(rx, ry);
                    *(uint32_t*)(dL + idx) = bpack(rx - bhi(rx), ry - bhi(ry));
                }
            }
    } else {
#pragma unroll
        for (int mt = 0; mt < 4; mt++)
#pragma unroll
            for (int hh = 0; hh < 2; hh++) {
                const int m = m0 + wm*64 + mt*16 + hh*8 + g;
#pragma unroll
                for (int nt = 0; nt < 4; nt++) {
                    const int colg = n0 + wn*32 + nt*8 + 2*tig;
                    float2 r;
                    r.x = acc[mt][nt][hh*2];
                    r.y = acc[mt][nt][hh*2 + 1];
                    *(float2*)(Cout + (size_t)m * 1024 + colg) = r;
                }
            }
    }
}

// ---------------------------------------------------------------------------
// Tensor-core flash attention (R10 WIN version; epilogue now emits fp16 hi/lo)
// ---------------------------------------------------------------------------
#define FTILE 9216            // 64 rows * 144 B (72-bf16 stride)
#define FSTG  (4*FTILE)
#define FLASH_SMEM (2*FSTG)   // 73728

__global__ __launch_bounds__(256) void flash_mma_kernel() {
    extern __shared__ char fsm[];
    const uint32_t sb = smem_u32(fsm);
    const int tid = threadIdx.x, lane = tid & 31, w = tid >> 5;
    const int qb = 15 - (int)blockIdx.x;
    const int bh = blockIdx.y;
    const int quad = lane >> 3, qi = lane & 7;
    const int g = lane >> 2, tig = lane & 3;

    const size_t bhoff = (size_t)bh * PS * PDH;
    const __nv_bfloat16* Kh0 = gk_h + bhoff;
    const __nv_bfloat16* Kl0 = gk_l + bhoff;
    const __nv_bfloat16* Vh0 = gv_h + bhoff;
    const __nv_bfloat16* Vl0 = gv_l + bhoff;

    {
        const int r = tid & 127;
        const __nv_bfloat16* src = (tid < 128 ? gq_h : gq_l) + bhoff + (size_t)(qb*128 + r)*PDH;
        uint32_t dst = sb + (tid < 128 ? 0u : 18432u) + (uint32_t)r*144;
#pragma unroll
        for (int u = 0; u < 8; u++) cp16(dst + u*16, (const char*)src + u*16);
        CP_COMMIT();
    }
    CP_WAIT0();
    __syncthreads();

    uint32_t qH[4][4], qL[4][4];
    {
        const uint32_t ao = (uint32_t)((w*16 + (quad&1)*8 + qi)*144 + (quad>>1)*16);
#pragma unroll
        for (int kd = 0; kd < 4; kd++) {
            ldm_x4(qH[kd], sb + ao + kd*32);
            ldm_x4(qL[kd], sb + 18432 + ao + kd*32);
        }
    }
    __syncthreads();

    const int jmax = 2*qb + 1;

    auto load_kv = [&](int j, int stg) {
        const int t = tid >> 6;
        const int r = tid & 63;
        const __nv_bfloat16* src =
            (t == 0 ? Kh0 : t == 1 ? Kl0 : t == 2 ? Vh0 : Vl0) + (size_t)(j*64 + r)*PDH;
        uint32_t dst = sb + stg*FSTG + t*FTILE + (uint32_t)r*144;
#pragma unroll
        for (int u = 0; u < 8; u++) cp16(dst + u*16, (const char*)src + u*16);
        CP_COMMIT();
    };

    float o[8][4];
#pragma unroll
    for (int t = 0; t < 8; t++) { o[t][0]=0.f; o[t][1]=0.f; o[t][2]=0.f; o[t][3]=0.f; }
    float m0 = -1e30f, m1 = -1e30f, l0 = 0.f, l1 = 0.f;
    const int row0 = qb*128 + w*16 + g;

    load_kv(0, 0);

    for (int j = 0; j <= jmax; j++) {
        const int stg = j & 1;
        if (j < jmax) { load_kv(j + 1, stg ^ 1); CP_WAIT1(); }
        else CP_WAIT0();
        __syncthreads();

        const uint32_t KhB = sb + stg*FSTG;
        const uint32_t KlB = KhB + FTILE;
        const uint32_t VhB = KhB + 2*FTILE;
        const uint32_t VlB = KhB + 3*FTILE;

        float sc[8][4];
#pragma unroll
        for (int t = 0; t < 8; t++) { sc[t][0]=0.f; sc[t][1]=0.f; sc[t][2]=0.f; sc[t][3]=0.f; }

        const uint32_t bo = (uint32_t)(((quad>>1)*8 + qi)*144 + (quad&1)*16);
#pragma unroll
        for (int kd = 0; kd < 4; kd++) {
            uint32_t bKh[4][4], bKl[4][4];
#pragma unroll
            for (int p = 0; p < 4; p++) {
                ldm_x4(bKh[p], KhB + bo + p*(16*144) + kd*32);
                ldm_x4(bKl[p], KlB + bo + p*(16*144) + kd*32);
            }
#pragma unroll
            for (int t = 0; t < 8; t++) {
                const uint32_t* ph = &bKh[t>>1][(t&1)*2];
                const uint32_t* pl = &bKl[t>>1][(t&1)*2];
                mma16816(sc[t], qH[kd], ph);
                mma16816(sc[t], qH[kd], pl);
                mma16816(sc[t], qL[kd], ph);
            }
        }

        if (j*64 + 63 > qb*128 + w*16) {
#pragma unroll
            for (int t = 0; t < 8; t++) {
                const int colb = j*64 + t*8 + 2*tig;
#pragma unroll
                for (int e = 0; e < 4; e++) {
                    const int col = colb + (e & 1);
                    const int row = row0 + ((e >= 2) ? 8 : 0);
                    sc[t][e] = (col > row) ? -1e30f : sc[t][e] * 0.125f;
                }
            }
        } else {
#pragma unroll
            for (int t = 0; t < 8; t++) {
                sc[t][0] *= 0.125f; sc[t][1] *= 0.125f;
                sc[t][2] *= 0.125f; sc[t][3] *= 0.125f;
            }
        }

        float rm0 = -1e30f, rm1 = -1e30f;
#pragma unroll
        for (int t = 0; t < 8; t++) {
            rm0 = fmaxf(rm0, fmaxf(sc[t][0], sc[t][1]));
            rm1 = fmaxf(rm1, fmaxf(sc[t][2], sc[t][3]));
        }
        rm0 = fmaxf(rm0, __shfl_xor_sync(0xffffffffu, rm0, 1));
        rm0 = fmaxf(rm0, __shfl_xor_sync(0xffffffffu, rm0, 2));
        rm1 = fmaxf(rm1, __shfl_xor_sync(0xffffffffu, rm1, 1));
        rm1 = fmaxf(rm1, __shfl_xor_sync(0xffffffffu, rm1, 2));
        const float mn0 = fmaxf(m0, rm0), mn1 = fmaxf(m1, rm1);
        const float a0 = fexp(m0 - mn0), a1 = fexp(m1 - mn1);
        float s0 = 0.f, s1 = 0.f;
#pragma unroll
        for (int t = 0; t < 8; t++) {
            sc[t][0] = fexp(sc[t][0] - mn0); sc[t][1] = fexp(sc[t][1] - mn0);
            sc[t][2] = fexp(sc[t][2] - mn1); sc[t][3] = fexp(sc[t][3] - mn1);
            s0 += sc[t][0] + sc[t][1];
            s1 += sc[t][2] + sc[t][3];
        }
        s0 += __shfl_xor_sync(0xffffffffu, s0, 1);
        s0 += __shfl_xor_sync(0xffffffffu, s0, 2);
        s1 += __shfl_xor_sync(0xffffffffu, s1, 1);
        s1 += __shfl_xor_sync(0xffffffffu, s1, 2);
        l0 = l0 * a0 + s0; l1 = l1 * a1 + s1;
        m0 = mn0; m1 = mn1;
#pragma unroll
        for (int t = 0; t < 8; t++) {
            o[t][0] *= a0; o[t][1] *= a0; o[t][2] *= a1; o[t][3] *= a1;
        }

        const uint32_t vo = (uint32_t)(((quad&1)*8 + qi)*144 + (quad>>1)*16);
#pragma unroll
        for (int kk = 0; kk < 4; kk++) {
            const int t0 = 2*kk, t1 = 2*kk + 1;
            uint32_t aph[4], apl[4];
            aph[0] = bpack(sc[t0][0], sc[t0][1]);
            aph[1] = bpack(sc[t0][2], sc[t0][3]);
            aph[2] = bpack(sc[t1][0], sc[t1][1]);
            aph[3] = bpack(sc[t1][2], sc[t1][3]);
            apl[0] = bpack(sc[t0][0]-bhi(sc[t0][0]), sc[t0][1]-bhi(sc[t0][1]));
            apl[1] = bpack(sc[t0][2]-bhi(sc[t0][2]), sc[t0][3]-bhi(sc[t0][3]));
            apl[2] = bpack(sc[t1][0]-bhi(sc[t1][0]), sc[t1][1]-bhi(sc[t1][1]));
            apl[3] = bpack(sc[t1][2]-bhi(sc[t1][2]), sc[t1][3]-bhi(sc[t1][3]));

            uint32_t bVh[4][4], bVl[4][4];
#pragma unroll
            for (int dp = 0; dp < 4; dp++) {
                ldm_x4_t(bVh[dp], VhB + vo + kk*(16*144) + dp*32);
                ldm_x4_t(bVl[dp], VlB + vo + kk*(16*144) + dp*32);
            }
#pragma unroll
            for (int dt = 0; dt < 8; dt++) {
                const uint32_t* ph = &bVh[dt>>1][(dt&1)*2];
                const uint32_t* pl = &bVl[dt>>1][(dt&1)*2];
                mma16816(o[dt], aph, ph);
                mma16816(o[dt], apl, ph);
                mma16816(o[dt], aph, pl);
            }
        }
        __syncthreads();
    }

    // epilogue: normalize, write fp16 hi/lo attn output for out-proj
    const float inv0 = 1.0f / l0, inv1 = 1.0f / l1;
    const int b = bh >> 4, h = bh & 15;
    const int s0r = qb*128 + w*16 + g;
    const int s1r = s0r + 8;
#pragma unroll
    for (int t = 0; t < 8; t++) {
        const float x0 = o[t][0]*inv0, x1 = o[t][1]*inv0;
        const float y0 = o[t][2]*inv1, y1 = o[t][3]*inv1;
        const int col = h*64 + t*8 + 2*tig;
        const size_t i0 = ((size_t)(b*PS + s0r))*PD + col;
        const size_t i1 = ((size_t)(b*PS + s1r))*PD + col;
        *(uint32_t*)(g_ah16 + i0) = hpack(x0, x1);
        *(uint32_t*)(g_al16 + i0) = hpack(x0 - hval(x0), x1 - hval(x1));
        *(uint32_t*)(g_ah16 + i1) = hpack(y0, y1);
        *(uint32_t*)(g_al16 + i1) = hpack(y0 - hval(y0), y1 - hval(y1));
    }
}

// ---------------------------------------------------------------------------
extern "C" void kernel_launch(void* const* d_in, const int* in_sizes, int n_in,
                              void* d_out, int out_size) {
    const float* x     = (const float*)d_in[0];
    const float* W_qkv = (const float*)d_in[1];
    const float* W_o   = (const float*)d_in[2];
    const int*   tpos  = (const int*)d_in[3];
    float* out = (float*)d_out;

    cudaFuncSetAttribute(flash_mma_kernel,
                         cudaFuncAttributeMaxDynamicSharedMemorySize, FLASH_SMEM);
    cudaFuncSetAttribute(mma_gemm_kernel<0>,
                         cudaFuncAttributeMaxDynamicSharedMemorySize, GEMM_SMEM);
    cudaFuncSetAttribute(mma_gemm_kernel<1>,
                         cudaFuncAttributeMaxDynamicSharedMemorySize, GEMM_SMEM);

    rope_table_kernel<<<64, 1024>>>(tpos);
    split_x_kernel<<<8192, 256>>>(x);
    cvt_wq_kernel<<<3072, 256>>>(W_qkv);
    cvt_wo_kernel<<<1024, 256>>>(W_o);

    mma_gemm_kernel<0><<<dim3(24, 64), 256, GEMM_SMEM>>>(nullptr);   // QKV + RoPE + splits
    flash_mma_kernel<<<dim3(16, 64), 256, FLASH_SMEM>>>();
    mma_gemm_kernel<1><<<dim3(8, 64), 256, GEMM_SMEM>>>(out);        // out proj
}

// round 13
// speedup vs baseline: 1.6527x; 1.2304x over previous
#include <cuda_runtime.h>
#include <cuda_bf16.h>
#include <cuda_fp16.h>
#include <math.h>
#include <stdint.h>

// Problem constants
#define PB 4
#define PS 2048
#define PD 1024
#define PH 16
#define PDH 64

// ---------------------------------------------------------------------------
// Scratch (device globals — no allocations allowed)
// ---------------------------------------------------------------------------
__device__ float g_cos[PS*32];
__device__ float g_sin[PS*32];

// fp16 operands for projection GEMMs (activation hi/lo split, weight single)
__device__ __half g_xh16[8192*1024], g_xl16[8192*1024];
__device__ __half g_wq16[3072*1024];
__device__ __half g_wo16[1024*1024];
__device__ __half g_ah16[8192*1024], g_al16[8192*1024];   // attn out (flash epilogue)

// q/k/v fp16 for flash: q hi/lo split, k single, v single. [b*H+h][s][dh]
__device__ __half gq_h16[PB*PH*PS*PDH], gq_l16[PB*PH*PS*PDH];
__device__ __half gk16[PB*PH*PS*PDH];
__device__ __half gv16[PB*PH*PS*PDH];

// ---------------------------------------------------------------------------
// Portable PTX helpers
// ---------------------------------------------------------------------------
__device__ __forceinline__ uint32_t smem_u32(const void* p) {
    uint32_t a;
    asm("{ .reg .u64 t; cvta.to.shared.u64 t, %1; cvt.u32.u64 %0, t; }"
        : "=r"(a) : "l"(p));
    return a;
}

__device__ __forceinline__ void cp16(uint32_t saddr, const void* gaddr) {
    asm volatile("cp.async.cg.shared.global [%0], [%1], 16;"
                 :: "r"(saddr), "l"(gaddr) : "memory");
}
#define CP_COMMIT() asm volatile("cp.async.commit_group;" ::: "memory")
#define CP_WAIT0()  asm volatile("cp.async.wait_group 0;" ::: "memory")
#define CP_WAIT1()  asm volatile("cp.async.wait_group 1;" ::: "memory")

__device__ __forceinline__ void ldm_x4(uint32_t* r, uint32_t addr) {
    asm volatile("ldmatrix.sync.aligned.m8n8.x4.shared.b16 {%0,%1,%2,%3}, [%4];"
        : "=r"(r[0]), "=r"(r[1]), "=r"(r[2]), "=r"(r[3]) : "r"(addr));
}
__device__ __forceinline__ void ldm_x4_t(uint32_t* r, uint32_t addr) {
    asm volatile("ldmatrix.sync.aligned.m8n8.x4.trans.shared.b16 {%0,%1,%2,%3}, [%4];"
        : "=r"(r[0]), "=r"(r[1]), "=r"(r[2]), "=r"(r[3]) : "r"(addr));
}

// fp16 inputs, f32 acc
__device__ __forceinline__ void mma16816h(float* d, const uint32_t* a, const uint32_t* b) {
    asm volatile(
        "mma.sync.aligned.m16n8k16.row.col.f32.f16.f16.f32 "
        "{%0,%1,%2,%3}, {%4,%5,%6,%7}, {%8,%9}, {%0,%1,%2,%3};"
        : "+f"(d[0]), "+f"(d[1]), "+f"(d[2]), "+f"(d[3])
        : "r"(a[0]), "r"(a[1]), "r"(a[2]), "r"(a[3]), "r"(b[0]), "r"(b[1]));
}

__device__ __forceinline__ uint32_t hpack(float a, float b) {
    __half2 h = __floats2half2_rn(a, b);
    return *(uint32_t*)&h;
}
__device__ __forceinline__ float hval(float a) {
    return __half2float(__float2half_rn(a));
}

// Fast exp on FMA pipe (valid for x <= ~0, clamps at -87)
__device__ __forceinline__ float fexp(float x) {
    float xc = fmaxf(x, -87.0f);
    float t  = fmaf(xc, 1.4426950408889634f, 12582912.0f);
    float n  = t - 12582912.0f;
    float r  = fmaf(n, -0.6931471805599453f, xc);
    float p  = 8.3333333e-3f;
    p = fmaf(p, r, 4.1666667e-2f);
    p = fmaf(p, r, 1.6666667e-1f);
    p = fmaf(p, r, 5.0e-1f);
    p = fmaf(p, r, 1.0f);
    p = fmaf(p, r, 1.0f);
    float s = __int_as_float((__float_as_int(t) << 23) + 0x3f800000);
    return p * s;
}

// ---------------------------------------------------------------------------
// RoPE table (fp64 for fidelity)
// ---------------------------------------------------------------------------
__global__ void rope_table_kernel(const int* __restrict__ pos) {
    int idx = blockIdx.x * blockDim.x + threadIdx.x;   // 65536
    int s = idx >> 5;
    int i = idx & 31;
    double p = (double)pos[s];
    double inv = exp(-((double)(2 * i) / 64.0) * log(10000.0));
    double a = p * inv;
    g_cos[idx] = (float)cos(a);
    g_sin[idx] = (float)sin(a);
}

// ---------------------------------------------------------------------------
// Conversions
// ---------------------------------------------------------------------------
__global__ void split_x_kernel(const float* __restrict__ x) {
    int i = blockIdx.x * blockDim.x + threadIdx.x;
    float4 v = ((const float4*)x)[i];
    ((uint32_t*)g_xh16)[i*2]   = hpack(v.x, v.y);
    ((uint32_t*)g_xh16)[i*2+1] = hpack(v.z, v.w);
    ((uint32_t*)g_xl16)[i*2]   = hpack(v.x - hval(v.x), v.y - hval(v.y));
    ((uint32_t*)g_xl16)[i*2+1] = hpack(v.z - hval(v.z), v.w - hval(v.w));
}
__global__ void cvt_wq_kernel(const float* __restrict__ w) {
    int i = blockIdx.x * blockDim.x + threadIdx.x;
    float4 v = ((const float4*)w)[i];
    ((uint32_t*)g_wq16)[i*2]   = hpack(v.x, v.y);
    ((uint32_t*)g_wq16)[i*2+1] = hpack(v.z, v.w);
}
__global__ void cvt_wo_kernel(const float* __restrict__ w) {
    int i = blockIdx.x * blockDim.x + threadIdx.x;
    float4 v = ((const float4*)w)[i];
    ((uint32_t*)g_wo16)[i*2]   = hpack(v.x, v.y);
    ((uint32_t*)g_wo16)[i*2+1] = hpack(v.z, v.w);
}

// ---------------------------------------------------------------------------
// fp16 mma GEMM: 128x128 CTA tile, BK=32, 256 threads, warp tile 64x32,
// 2-stage cp.async pipeline. 2-term: Ah*B + Al*B.
// MODE 0: A=x, B=W_qkv; epilogue RoPE; q -> fp16 hi/lo, k,v -> fp16 single.
// MODE 1: A=attn (fp16 split), B=W_o, epilogue fp32 store into Cout.
// ---------------------------------------------------------------------------
#define LDT 40
#define TILE_B (128*LDT*2)        // 10240 B
#define STAGE_B (3*TILE_B)        // Ah, Al, B = 30720 B
#define GEMM_SMEM (2*STAGE_B)     // 61440 B

template<int MODE>
__global__ __launch_bounds__(256)
void mma_gemm_kernel(float* __restrict__ Cout)
{
    const __half *Ahp, *Alp, *Bp;
    if (MODE == 0) { Ahp = g_xh16; Alp = g_xl16; Bp = g_wq16; }
    else           { Ahp = g_ah16; Alp = g_al16; Bp = g_wo16; }

    extern __shared__ char dsm[];
    const uint32_t sBase = smem_u32(dsm);

    const int tid = threadIdx.x;
    const int n0 = blockIdx.x * 128;
    const int m0 = blockIdx.y * 128;
    const int lane = tid & 31, w = tid >> 5;
    const int wm = w >> 2, wn = w & 3;

    const int lr = tid >> 1, lh = tid & 1;
    const __half* gAh = Ahp + (size_t)(m0 + lr) * 1024 + lh * 16;
    const __half* gAl = Alp + (size_t)(m0 + lr) * 1024 + lh * 16;
    const __half* gB  = Bp  + (size_t)(n0 + lr) * 1024 + lh * 16;
    const uint32_t sOff = (uint32_t)((lr * LDT + lh * 16) * 2);

    const int quad = lane >> 3, qi = lane & 7;
    const uint32_t aoff = (uint32_t)(((wm*64 + (quad&1)*8 + qi) * LDT + (quad>>1)*8) * 2);
    const uint32_t boff = (uint32_t)(((wn*32 + (quad>>1)*8 + qi) * LDT + (quad&1)*8) * 2);

    float acc[4][4][4];
#pragma unroll
    for (int a = 0; a < 4; a++)
#pragma unroll
        for (int b = 0; b < 4; b++)
#pragma unroll
            for (int c = 0; c < 4; c++) acc[a][b][c] = 0.0f;

    auto load_stage = [&](int kt, int stg) {
        const int kb = kt * 32;
        const uint32_t s0 = sBase + stg * STAGE_B + sOff;
        cp16(s0,                gAh + kb);  cp16(s0 + 16,            gAh + kb + 8);
        cp16(s0 + TILE_B,       gAl + kb);  cp16(s0 + TILE_B + 16,   gAl + kb + 8);
        cp16(s0 + 2*TILE_B,     gB  + kb);  cp16(s0 + 2*TILE_B + 16, gB  + kb + 8);
        CP_COMMIT();
    };

    load_stage(0, 0);

    for (int kt = 0; kt < 32; kt++) {
        const int stg = kt & 1;
        if (kt + 1 < 32) { load_stage(kt + 1, stg ^ 1); CP_WAIT1(); }
        else CP_WAIT0();
        __syncthreads();

        const uint32_t sAhB = sBase + stg * STAGE_B;
        const uint32_t sAlB = sAhB + TILE_B;
        const uint32_t sBB  = sAhB + 2*TILE_B;

#pragma unroll
        for (int ks = 0; ks < 2; ks++) {
            const uint32_t kso = ks * 32;
            uint32_t aH[4][4], aL[4][4], bB[2][4];
#pragma unroll
            for (int mt = 0; mt < 4; mt++) {
                ldm_x4(aH[mt], sAhB + aoff + mt * (16*LDT*2) + kso);
                ldm_x4(aL[mt], sAlB + aoff + mt * (16*LDT*2) + kso);
            }
#pragma unroll
            for (int np = 0; np < 2; np++)
                ldm_x4(bB[np], sBB + boff + np * (16*LDT*2) + kso);
#pragma unroll
            for (int mt = 0; mt < 4; mt++)
#pragma unroll
                for (int nt = 0; nt < 4; nt++) {
                    const uint32_t* pb = &bB[nt >> 1][(nt & 1) * 2];
                    mma16816h(acc[mt][nt], aH[mt], pb);
                    mma16816h(acc[mt][nt], aL[mt], pb);
                }
        }
        __syncthreads();
    }

    const int g = lane >> 2, tig = lane & 3;
    if (MODE == 0) {
        const int kmat = n0 >> 10;                   // 0=q 1=k 2=v
#pragma unroll
        for (int mt = 0; mt < 4; mt++)
#pragma unroll
            for (int hh = 0; hh < 2; hh++) {
                const int m = m0 + wm*64 + mt*16 + hh*8 + g;
                const int b = m >> 11, s = m & 2047;
#pragma unroll
                for (int nt = 0; nt < 4; nt++) {
                    const int colg = n0 + wn*32 + nt*8 + 2*tig;
                    const int h = (colg >> 6) & 15;
                    const int cc = colg & 63;
                    const float v0 = acc[mt][nt][hh*2];
                    const float v1 = acc[mt][nt][hh*2 + 1];
                    float rx, ry;
                    if (kmat < 2) {
                        const int pi = (s << 5) + (cc >> 1);
                        const float c_ = g_cos[pi], s_ = g_sin[pi];
                        rx = v0 * c_ - v1 * s_;
                        ry = v0 * s_ + v1 * c_;
                    } else {
                        rx = v0; ry = v1;
                    }
                    size_t idx = ((size_t)((b*PH + h)*PS + s))*PDH + cc;
                    if (kmat == 0) {
                        *(uint32_t*)(gq_h16 + idx) = hpack(rx, ry);
                        *(uint32_t*)(gq_l16 + idx) = hpack(rx - hval(rx), ry - hval(ry));
                    } else if (kmat == 1) {
                        *(uint32_t*)(gk16 + idx) = hpack(rx, ry);
                    } else {
                        *(uint32_t*)(gv16 + idx) = hpack(rx, ry);
                    }
                }
            }
    } else {
#pragma unroll
        for (int mt = 0; mt < 4; mt++)
#pragma unroll
            for (int hh = 0; hh < 2; hh++) {
                const int m = m0 + wm*64 + mt*16 + hh*8 + g;
#pragma unroll
                for (int nt = 0; nt < 4; nt++) {
                    const int colg = n0 + wn*32 + nt*8 + 2*tig;
                    float2 r;
                    r.x = acc[mt][nt][hh*2];
                    r.y = acc[mt][nt][hh*2 + 1];
                    *(float2*)(Cout + (size_t)m * 1024 + colg) = r;
                }
            }
    }
}

// ---------------------------------------------------------------------------
// Tensor-core flash attention, fp16 2-term.
// q-tile 128 (8 warps x m16), k-tile 64.
// Scores: (Qh + Ql) * K      (2 MMAs per tile pair, fp32 acc)
// PV:     (Ph + Pl) * V      (2 MMAs, V single fp16, ldmatrix.trans)
// K/V double-buffered cp.async (2 tiles/stage); Q staged once -> registers.
// Output written fp16 hi/lo to g_ah16/g_al16 [b][s][h*64+c].
// ---------------------------------------------------------------------------
#define FTILE 9216            // 64 rows * 144 B (72-fp16 stride)
#define FSTG  (2*FTILE)       // K, V = 18432
#define FLASH_SMEM (2*FSTG)   // 36864

__global__ __launch_bounds__(256) void flash_mma_kernel() {
    extern __shared__ char fsm[];
    const uint32_t sb = smem_u32(fsm);
    const int tid = threadIdx.x, lane = tid & 31, w = tid >> 5;
    const int qb = 15 - (int)blockIdx.x;       // heavy CTAs first
    const int bh = blockIdx.y;
    const int quad = lane >> 3, qi = lane & 7;
    const int g = lane >> 2, tig = lane & 3;

    const size_t bhoff = (size_t)bh * PS * PDH;
    const __half* K0 = gk16 + bhoff;
    const __half* V0 = gv16 + bhoff;

    // ---- stage Q (hi at sb, lo at sb+18432), ldmatrix into registers ----
    {
        const int r = tid & 127;
        const __half* src = (tid < 128 ? gq_h16 : gq_l16) + bhoff + (size_t)(qb*128 + r)*PDH;
        uint32_t dst = sb + (tid < 128 ? 0u : 18432u) + (uint32_t)r*144;
#pragma unroll
        for (int u = 0; u < 8; u++) cp16(dst + u*16, (const char*)src + u*16);
        CP_COMMIT();
    }
    CP_WAIT0();
    __syncthreads();

    uint32_t qH[4][4], qL[4][4];
    {
        const uint32_t ao = (uint32_t)((w*16 + (quad&1)*8 + qi)*144 + (quad>>1)*16);
#pragma unroll
        for (int kd = 0; kd < 4; kd++) {
            ldm_x4(qH[kd], sb + ao + kd*32);
            ldm_x4(qL[kd], sb + 18432 + ao + kd*32);
        }
    }
    __syncthreads();   // staging area free for K/V

    const int jmax = 2*qb + 1;

    // 2 tiles (K,V), 64 rows each; 256 threads -> thread covers half a row
    auto load_kv = [&](int j, int stg) {
        const int t = tid >> 7;            // 0 K, 1 V
        const int rr = tid & 127;
        const int row = rr >> 1, hf = rr & 1;
        const __half* src = (t == 0 ? K0 : V0) + (size_t)(j*64 + row)*PDH + hf*32;
        uint32_t dst = sb + stg*FSTG + t*FTILE + (uint32_t)row*144 + hf*64;
#pragma unroll
        for (int u = 0; u < 4; u++) cp16(dst + u*16, (const char*)src + u*16);
        CP_COMMIT();
    };

    float o[8][4];
#pragma unroll
    for (int t = 0; t < 8; t++) { o[t][0]=0.f; o[t][1]=0.f; o[t][2]=0.f; o[t][3]=0.f; }
    float m0 = -1e30f, m1 = -1e30f, l0 = 0.f, l1 = 0.f;
    const int row0 = qb*128 + w*16 + g;

    load_kv(0, 0);

    for (int j = 0; j <= jmax; j++) {
        const int stg = j & 1;
        if (j < jmax) { load_kv(j + 1, stg ^ 1); CP_WAIT1(); }
        else CP_WAIT0();
        __syncthreads();

        const uint32_t KB = sb + stg*FSTG;
        const uint32_t VB = KB + FTILE;

        // ---- QK^T: (Qh + Ql) * K ----
        float sc[8][4];
#pragma unroll
        for (int t = 0; t < 8; t++) { sc[t][0]=0.f; sc[t][1]=0.f; sc[t][2]=0.f; sc[t][3]=0.f; }

        const uint32_t bo = (uint32_t)(((quad>>1)*8 + qi)*144 + (quad&1)*16);
#pragma unroll
        for (int kd = 0; kd < 4; kd++) {
            uint32_t bK[4][4];
#pragma unroll
            for (int p = 0; p < 4; p++)
                ldm_x4(bK[p], KB + bo + p*(16*144) + kd*32);
#pragma unroll
            for (int t = 0; t < 8; t++) {
                const uint32_t* pk = &bK[t>>1][(t&1)*2];
                mma16816h(sc[t], qH[kd], pk);
                mma16816h(sc[t], qL[kd], pk);
            }
        }

        // ---- scale + causal mask ----
        if (j*64 + 63 > qb*128 + w*16) {
#pragma unroll
            for (int t = 0; t < 8; t++) {
                const int colb = j*64 + t*8 + 2*tig;
#pragma unroll
                for (int e = 0; e < 4; e++) {
                    const int col = colb + (e & 1);
                    const int row = row0 + ((e >= 2) ? 8 : 0);
                    sc[t][e] = (col > row) ? -1e30f : sc[t][e] * 0.125f;
                }
            }
        } else {
#pragma unroll
            for (int t = 0; t < 8; t++) {
                sc[t][0] *= 0.125f; sc[t][1] *= 0.125f;
                sc[t][2] *= 0.125f; sc[t][3] *= 0.125f;
            }
        }

        // ---- online softmax (rows g and g+8) ----
        float rm0 = -1e30f, rm1 = -1e30f;
#pragma unroll
        for (int t = 0; t < 8; t++) {
            rm0 = fmaxf(rm0, fmaxf(sc[t][0], sc[t][1]));
            rm1 = fmaxf(rm1, fmaxf(sc[t][2], sc[t][3]));
        }
        rm0 = fmaxf(rm0, __shfl_xor_sync(0xffffffffu, rm0, 1));
        rm0 = fmaxf(rm0, __shfl_xor_sync(0xffffffffu, rm0, 2));
        rm1 = fmaxf(rm1, __shfl_xor_sync(0xffffffffu, rm1, 1));
        rm1 = fmaxf(rm1, __shfl_xor_sync(0xffffffffu, rm1, 2));
        const float mn0 = fmaxf(m0, rm0), mn1 = fmaxf(m1, rm1);
        const float a0 = fexp(m0 - mn0), a1 = fexp(m1 - mn1);
        float s0 = 0.f, s1 = 0.f;
#pragma unroll
        for (int t = 0; t < 8; t++) {
            sc[t][0] = fexp(sc[t][0] - mn0); sc[t][1] = fexp(sc[t][1] - mn0);
            sc[t][2] = fexp(sc[t][2] - mn1); sc[t][3] = fexp(sc[t][3] - mn1);
            s0 += sc[t][0] + sc[t][1];
            s1 += sc[t][2] + sc[t][3];
        }
        s0 += __shfl_xor_sync(0xffffffffu, s0, 1);
        s0 += __shfl_xor_sync(0xffffffffu, s0, 2);
        s1 += __shfl_xor_sync(0xffffffffu, s1, 1);
        s1 += __shfl_xor_sync(0xffffffffu, s1, 2);
        l0 = l0 * a0 + s0; l1 = l1 * a1 + s1;
        m0 = mn0; m1 = mn1;
#pragma unroll
        for (int t = 0; t < 8; t++) {
            o[t][0] *= a0; o[t][1] *= a0; o[t][2] *= a1; o[t][3] *= a1;
        }

        // ---- PV: (Ph + Pl) * V, V single fp16 via ldmatrix.trans ----
        const uint32_t vo = (uint32_t)(((quad&1)*8 + qi)*144 + (quad>>1)*16);
#pragma unroll
        for (int kk = 0; kk < 4; kk++) {
            const int t0 = 2*kk, t1 = 2*kk + 1;
            uint32_t aph[4], apl[4];
            aph[0] = hpack(sc[t0][0], sc[t0][1]);
            aph[1] = hpack(sc[t0][2], sc[t0][3]);
            aph[2] = hpack(sc[t1][0], sc[t1][1]);
            aph[3] = hpack(sc[t1][2], sc[t1][3]);
            apl[0] = hpack(sc[t0][0]-hval(sc[t0][0]), sc[t0][1]-hval(sc[t0][1]));
            apl[1] = hpack(sc[t0][2]-hval(sc[t0][2]), sc[t0][3]-hval(sc[t0][3]));
            apl[2] = hpack(sc[t1][0]-hval(sc[t1][0]), sc[t1][1]-hval(sc[t1][1]));
            apl[3] = hpack(sc[t1][2]-hval(sc[t1][2]), sc[t1][3]-hval(sc[t1][3]));

            uint32_t bV[4][4];
#pragma unroll
            for (int dp = 0; dp < 4; dp++)
                ldm_x4_t(bV[dp], VB + vo + kk*(16*144) + dp*32);
#pragma unroll
            for (int dt = 0; dt < 8; dt++) {
                const uint32_t* pv = &bV[dt>>1][(dt&1)*2];
                mma16816h(o[dt], aph, pv);
                mma16816h(o[dt], apl, pv);
            }
        }
        __syncthreads();
    }

    // ---- epilogue: normalize, write fp16 hi/lo attn output ----
    const float inv0 = 1.0f / l0, inv1 = 1.0f / l1;
    const int b = bh >> 4, h = bh & 15;
    const int s0r = qb*128 + w*16 + g;
    const int s1r = s0r + 8;
#pragma unroll
    for (int t = 0; t < 8; t++) {
        const float x0 = o[t][0]*inv0, x1 = o[t][1]*inv0;
        const float y0 = o[t][2]*inv1, y1 = o[t][3]*inv1;
        const int col = h*64 + t*8 + 2*tig;
        const size_t i0 = ((size_t)(b*PS + s0r))*PD + col;
        const size_t i1 = ((size_t)(b*PS + s1r))*PD + col;
        *(uint32_t*)(g_ah16 + i0) = hpack(x0, x1);
        *(uint32_t*)(g_al16 + i0) = hpack(x0 - hval(x0), x1 - hval(x1));
        *(uint32_t*)(g_ah16 + i1) = hpack(y0, y1);
        *(uint32_t*)(g_al16 + i1) = hpack(y0 - hval(y0), y1 - hval(y1));
    }
}

// ---------------------------------------------------------------------------
extern "C" void kernel_launch(void* const* d_in, const int* in_sizes, int n_in,
                              void* d_out, int out_size) {
    const float* x     = (const float*)d_in[0];
    const float* W_qkv = (const float*)d_in[1];
    const float* W_o   = (const float*)d_in[2];
    const int*   tpos  = (const int*)d_in[3];
    float* out = (float*)d_out;

    cudaFuncSetAttribute(flash_mma_kernel,
                         cudaFuncAttributeMaxDynamicSharedMemorySize, FLASH_SMEM);
    cudaFuncSetAttribute(mma_gemm_kernel<0>,
                         cudaFuncAttributeMaxDynamicSharedMemorySize, GEMM_SMEM);
    cudaFuncSetAttribute(mma_gemm_kernel<1>,
                         cudaFuncAttributeMaxDynamicSharedMemorySize, GEMM_SMEM);

    rope_table_kernel<<<64, 1024>>>(tpos);
    split_x_kernel<<<8192, 256>>>(x);
    cvt_wq_kernel<<<3072, 256>>>(W_qkv);
    cvt_wo_kernel<<<1024, 256>>>(W_o);

    mma_gemm_kernel<0><<<dim3(24, 64), 256, GEMM_SMEM>>>(nullptr);   // QKV + RoPE + cvt
    flash_mma_kernel<<<dim3(16, 64), 256, FLASH_SMEM>>>();
    mma_gemm_kernel<1><<<dim3(8, 64), 256, GEMM_SMEM>>>(out);        // out proj
}

// round 14
// speedup vs baseline: 1.7299x; 1.0467x over previous
#include <cuda_runtime.h>
#include <cuda_bf16.h>
#include <cuda_fp16.h>
#include <math.h>
#include <stdint.h>

// Problem constants
#define PB 4
#define PS 2048
#define PD 1024
#define PH 16
#define PDH 64

// ---------------------------------------------------------------------------
// Scratch (device globals — no allocations allowed)
// ---------------------------------------------------------------------------
__device__ float g_cos[PS*32];
__device__ float g_sin[PS*32];

__device__ __half g_xh16[8192*1024], g_xl16[8192*1024];
__device__ __half g_wq16[3072*1024];
__device__ __half g_wo16[1024*1024];
__device__ __half g_ah16[8192*1024];                      // attn out (single fp16)

// q/k/v fp16 for flash: q hi/lo split, k single, v single. [b*H+h][s][dh]
__device__ __half gq_h16[PB*PH*PS*PDH], gq_l16[PB*PH*PS*PDH];
__device__ __half gk16[PB*PH*PS*PDH];
__device__ __half gv16[PB*PH*PS*PDH];

// ---------------------------------------------------------------------------
// Portable PTX helpers
// ---------------------------------------------------------------------------
__device__ __forceinline__ uint32_t smem_u32(const void* p) {
    uint32_t a;
    asm("{ .reg .u64 t; cvta.to.shared.u64 t, %1; cvt.u32.u64 %0, t; }"
        : "=r"(a) : "l"(p));
    return a;
}

__device__ __forceinline__ void cp16(uint32_t saddr, const void* gaddr) {
    asm volatile("cp.async.cg.shared.global [%0], [%1], 16;"
                 :: "r"(saddr), "l"(gaddr) : "memory");
}
#define CP_COMMIT() asm volatile("cp.async.commit_group;" ::: "memory")
#define CP_WAIT0()  asm volatile("cp.async.wait_group 0;" ::: "memory")
#define CP_WAIT1()  asm volatile("cp.async.wait_group 1;" ::: "memory")
#define CP_WAIT2()  asm volatile("cp.async.wait_group 2;" ::: "memory")

__device__ __forceinline__ void ldm_x4(uint32_t* r, uint32_t addr) {
    asm volatile("ldmatrix.sync.aligned.m8n8.x4.shared.b16 {%0,%1,%2,%3}, [%4];"
        : "=r"(r[0]), "=r"(r[1]), "=r"(r[2]), "=r"(r[3]) : "r"(addr));
}
__device__ __forceinline__ void ldm_x4_t(uint32_t* r, uint32_t addr) {
    asm volatile("ldmatrix.sync.aligned.m8n8.x4.trans.shared.b16 {%0,%1,%2,%3}, [%4];"
        : "=r"(r[0]), "=r"(r[1]), "=r"(r[2]), "=r"(r[3]) : "r"(addr));
}

__device__ __forceinline__ void mma16816h(float* d, const uint32_t* a, const uint32_t* b) {
    asm volatile(
        "mma.sync.aligned.m16n8k16.row.col.f32.f16.f16.f32 "
        "{%0,%1,%2,%3}, {%4,%5,%6,%7}, {%8,%9}, {%0,%1,%2,%3};"
        : "+f"(d[0]), "+f"(d[1]), "+f"(d[2]), "+f"(d[3])
        : "r"(a[0]), "r"(a[1]), "r"(a[2]), "r"(a[3]), "r"(b[0]), "r"(b[1]));
}

__device__ __forceinline__ uint32_t hpack(float a, float b) {
    __half2 h = __floats2half2_rn(a, b);
    return *(uint32_t*)&h;
}
__device__ __forceinline__ float hval(float a) {
    return __half2float(__float2half_rn(a));
}

// Fast exp on FMA pipe (valid for x <= ~0, clamps at -87)
__device__ __forceinline__ float fexp(float x) {
    float xc = fmaxf(x, -87.0f);
    float t  = fmaf(xc, 1.4426950408889634f, 12582912.0f);
    float n  = t - 12582912.0f;
    float r  = fmaf(n, -0.6931471805599453f, xc);
    float p  = 8.3333333e-3f;
    p = fmaf(p, r, 4.1666667e-2f);
    p = fmaf(p, r, 1.6666667e-1f);
    p = fmaf(p, r, 5.0e-1f);
    p = fmaf(p, r, 1.0f);
    p = fmaf(p, r, 1.0f);
    float s = __int_as_float((__float_as_int(t) << 23) + 0x3f800000);
    return p * s;
}

// ---------------------------------------------------------------------------
// RoPE table (fp64 for fidelity)
// ---------------------------------------------------------------------------
__global__ void rope_table_kernel(const int* __restrict__ pos) {
    int idx = blockIdx.x * blockDim.x + threadIdx.x;   // 65536
    int s = idx >> 5;
    int i = idx & 31;
    double p = (double)pos[s];
    double inv = exp(-((double)(2 * i) / 64.0) * log(10000.0));
    double a = p * inv;
    g_cos[idx] = (float)cos(a);
    g_sin[idx] = (float)sin(a);
}

// ---------------------------------------------------------------------------
// Conversions
// ---------------------------------------------------------------------------
__global__ void split_x_kernel(const float* __restrict__ x) {
    int i = blockIdx.x * blockDim.x + threadIdx.x;
    float4 v = ((const float4*)x)[i];
    ((uint32_t*)g_xh16)[i*2]   = hpack(v.x, v.y);
    ((uint32_t*)g_xh16)[i*2+1] = hpack(v.z, v.w);
    ((uint32_t*)g_xl16)[i*2]   = hpack(v.x - hval(v.x), v.y - hval(v.y));
    ((uint32_t*)g_xl16)[i*2+1] = hpack(v.z - hval(v.z), v.w - hval(v.w));
}
__global__ void cvt_wq_kernel(const float* __restrict__ w) {
    int i = blockIdx.x * blockDim.x + threadIdx.x;
    float4 v = ((const float4*)w)[i];
    ((uint32_t*)g_wq16)[i*2]   = hpack(v.x, v.y);
    ((uint32_t*)g_wq16)[i*2+1] = hpack(v.z, v.w);
}
__global__ void cvt_wo_kernel(const float* __restrict__ w) {
    int i = blockIdx.x * blockDim.x + threadIdx.x;
    float4 v = ((const float4*)w)[i];
    ((uint32_t*)g_wo16)[i*2]   = hpack(v.x, v.y);
    ((uint32_t*)g_wo16)[i*2+1] = hpack(v.z, v.w);
}

// ---------------------------------------------------------------------------
// fp16 mma GEMM: 128x128 CTA tile, BK=32, 256 threads, warp tile 64x32,
// 3-stage cp.async pipeline.
// MODE 0: 2-term Ah*B + Al*B (A=x split, B=W_qkv). Epilogue RoPE;
//         q -> fp16 hi/lo, k,v -> fp16 single.
// MODE 1: 1-term A*B (A=attn fp16, B=W_o). Epilogue fp32 store.
// ---------------------------------------------------------------------------
#define LDT 40
#define TILE_B (128*LDT*2)                 // 10240 B
#define NTILES(M) ((M) == 0 ? 3 : 2)
#define STAGE_BM(M) (NTILES(M)*TILE_B)
#define GEMM_SMEM(M) (3*STAGE_BM(M))       // 92160 / 61440

template<int MODE>
__global__ __launch_bounds__(256)
void mma_gemm_kernel(float* __restrict__ Cout)
{
    constexpr int STAGE_B = STAGE_BM(MODE);

    const __half *Ahp, *Alp, *Bp;
    if (MODE == 0) { Ahp = g_xh16; Alp = g_xl16; Bp = g_wq16; }
    else           { Ahp = g_ah16; Alp = nullptr; Bp = g_wo16; }

    extern __shared__ char dsm[];
    const uint32_t sBase = smem_u32(dsm);

    const int tid = threadIdx.x;
    const int n0 = blockIdx.x * 128;
    const int m0 = blockIdx.y * 128;
    const int lane = tid & 31, w = tid >> 5;
    const int wm = w >> 2, wn = w & 3;

    const int lr = tid >> 1, lh = tid & 1;
    const __half* gAh = Ahp + (size_t)(m0 + lr) * 1024 + lh * 16;
    const __half* gAl = MODE == 0 ? (Alp + (size_t)(m0 + lr) * 1024 + lh * 16) : nullptr;
    const __half* gB  = Bp  + (size_t)(n0 + lr) * 1024 + lh * 16;
    const uint32_t sOff = (uint32_t)((lr * LDT + lh * 16) * 2);

    const int quad = lane >> 3, qi = lane & 7;
    const uint32_t aoff = (uint32_t)(((wm*64 + (quad&1)*8 + qi) * LDT + (quad>>1)*8) * 2);
    const uint32_t boff = (uint32_t)(((wn*32 + (quad>>1)*8 + qi) * LDT + (quad&1)*8) * 2);

    float acc[4][4][4];
#pragma unroll
    for (int a = 0; a < 4; a++)
#pragma unroll
        for (int b = 0; b < 4; b++)
#pragma unroll
            for (int c = 0; c < 4; c++) acc[a][b][c] = 0.0f;

    auto load_stage = [&](int kt, int stg) {
        const int kb = kt * 32;
        const uint32_t s0 = sBase + stg * STAGE_B + sOff;
        cp16(s0,      gAh + kb);  cp16(s0 + 16,      gAh + kb + 8);
        if (MODE == 0) {
            cp16(s0 + TILE_B,   gAl + kb);  cp16(s0 + TILE_B + 16,   gAl + kb + 8);
            cp16(s0 + 2*TILE_B, gB  + kb);  cp16(s0 + 2*TILE_B + 16, gB  + kb + 8);
        } else {
            cp16(s0 + TILE_B,   gB  + kb);  cp16(s0 + TILE_B + 16,   gB  + kb + 8);
        }
        CP_COMMIT();
    };

    load_stage(0, 0);
    load_stage(1, 1);

    for (int kt = 0; kt < 32; kt++) {
        const int stg = kt % 3;
        if (kt + 2 < 32) { load_stage(kt + 2, (kt + 2) % 3); CP_WAIT2(); }
        else if (kt + 1 < 32) CP_WAIT1();
        else CP_WAIT0();
        __syncthreads();

        const uint32_t sAhB = sBase + stg * STAGE_B;
        const uint32_t sAlB = sAhB + TILE_B;                       // MODE 0 only
        const uint32_t sBB  = sAhB + (MODE == 0 ? 2 : 1) * TILE_B;

#pragma unroll
        for (int ks = 0; ks < 2; ks++) {
            const uint32_t kso = ks * 32;
            uint32_t aH[4][4], aL[4][4], bB[2][4];
#pragma unroll
            for (int mt = 0; mt < 4; mt++) {
                ldm_x4(aH[mt], sAhB + aoff + mt * (16*LDT*2) + kso);
                if (MODE == 0) ldm_x4(aL[mt], sAlB + aoff + mt * (16*LDT*2) + kso);
            }
#pragma unroll
            for (int np = 0; np < 2; np++)
                ldm_x4(bB[np], sBB + boff + np * (16*LDT*2) + kso);
#pragma unroll
            for (int mt = 0; mt < 4; mt++)
#pragma unroll
                for (int nt = 0; nt < 4; nt++) {
                    const uint32_t* pb = &bB[nt >> 1][(nt & 1) * 2];
                    mma16816h(acc[mt][nt], aH[mt], pb);
                    if (MODE == 0) mma16816h(acc[mt][nt], aL[mt], pb);
                }
        }
        __syncthreads();
    }

    const int g = lane >> 2, tig = lane & 3;
    if (MODE == 0) {
        const int kmat = n0 >> 10;                   // 0=q 1=k 2=v
#pragma unroll
        for (int mt = 0; mt < 4; mt++)
#pragma unroll
            for (int hh = 0; hh < 2; hh++) {
                const int m = m0 + wm*64 + mt*16 + hh*8 + g;
                const int b = m >> 11, s = m & 2047;
#pragma unroll
                for (int nt = 0; nt < 4; nt++) {
                    const int colg = n0 + wn*32 + nt*8 + 2*tig;
                    const int h = (colg >> 6) & 15;
                    const int cc = colg & 63;
                    const float v0 = acc[mt][nt][hh*2];
                    const float v1 = acc[mt][nt][hh*2 + 1];
                    float rx, ry;
                    if (kmat < 2) {
                        const int pi = (s << 5) + (cc >> 1);
                        const float c_ = g_cos[pi], s_ = g_sin[pi];
                        rx = v0 * c_ - v1 * s_;
                        ry = v0 * s_ + v1 * c_;
                    } else {
                        rx = v0; ry = v1;
                    }
                    size_t idx = ((size_t)((b*PH + h)*PS + s))*PDH + cc;
                    if (kmat == 0) {
                        *(uint32_t*)(gq_h16 + idx) = hpack(rx, ry);
                        *(uint32_t*)(gq_l16 + idx) = hpack(rx - hval(rx), ry - hval(ry));
                    } else if (kmat == 1) {
                        *(uint32_t*)(gk16 + idx) = hpack(rx, ry);
                    } else {
                        *(uint32_t*)(gv16 + idx) = hpack(rx, ry);
                    }
                }
            }
    } else {
#pragma unroll
        for (int mt = 0; mt < 4; mt++)
#pragma unroll
            for (int hh = 0; hh < 2; hh++) {
                const int m = m0 + wm*64 + mt*16 + hh*8 + g;
#pragma unroll
                for (int nt = 0; nt < 4; nt++) {
                    const int colg = n0 + wn*32 + nt*8 + 2*tig;
                    float2 r;
                    r.x = acc[mt][nt][hh*2];
                    r.y = acc[mt][nt][hh*2 + 1];
                    *(float2*)(Cout + (size_t)m * 1024 + colg) = r;
                }
            }
    }
}

// ---------------------------------------------------------------------------
// Tensor-core flash attention, fp16 2-term (R13 WIN version).
// Output now single fp16 (out-proj is 1-term).
// ---------------------------------------------------------------------------
#define FTILE 9216            // 64 rows * 144 B (72-fp16 stride)
#define FSTG  (2*FTILE)       // K, V = 18432
#define FLASH_SMEM (2*FSTG)   // 36864

__global__ __launch_bounds__(256) void flash_mma_kernel() {
    extern __shared__ char fsm[];
    const uint32_t sb = smem_u32(fsm);
    const int tid = threadIdx.x, lane = tid & 31, w = tid >> 5;
    const int qb = 15 - (int)blockIdx.x;       // heavy CTAs first
    const int bh = blockIdx.y;
    const int quad = lane >> 3, qi = lane & 7;
    const int g = lane >> 2, tig = lane & 3;

    const size_t bhoff = (size_t)bh * PS * PDH;
    const __half* K0 = gk16 + bhoff;
    const __half* V0 = gv16 + bhoff;

    {
        const int r = tid & 127;
        const __half* src = (tid < 128 ? gq_h16 : gq_l16) + bhoff + (size_t)(qb*128 + r)*PDH;
        uint32_t dst = sb + (tid < 128 ? 0u : 18432u) + (uint32_t)r*144;
#pragma unroll
        for (int u = 0; u < 8; u++) cp16(dst + u*16, (const char*)src + u*16);
        CP_COMMIT();
    }
    CP_WAIT0();
    __syncthreads();

    uint32_t qH[4][4], qL[4][4];
    {
        const uint32_t ao = (uint32_t)((w*16 + (quad&1)*8 + qi)*144 + (quad>>1)*16);
#pragma unroll
        for (int kd = 0; kd < 4; kd++) {
            ldm_x4(qH[kd], sb + ao + kd*32);
            ldm_x4(qL[kd], sb + 18432 + ao + kd*32);
        }
    }
    __syncthreads();

    const int jmax = 2*qb + 1;

    auto load_kv = [&](int j, int stg) {
        const int t = tid >> 7;            // 0 K, 1 V
        const int rr = tid & 127;
        const int row = rr >> 1, hf = rr & 1;
        const __half* src = (t == 0 ? K0 : V0) + (size_t)(j*64 + row)*PDH + hf*32;
        uint32_t dst = sb + stg*FSTG + t*FTILE + (uint32_t)row*144 + hf*64;
#pragma unroll
        for (int u = 0; u < 4; u++) cp16(dst + u*16, (const char*)src + u*16);
        CP_COMMIT();
    };

    float o[8][4];
#pragma unroll
    for (int t = 0; t < 8; t++) { o[t][0]=0.f; o[t][1]=0.f; o[t][2]=0.f; o[t][3]=0.f; }
    float m0 = -1e30f, m1 = -1e30f, l0 = 0.f, l1 = 0.f;
    const int row0 = qb*128 + w*16 + g;

    load_kv(0, 0);

    for (int j = 0; j <= jmax; j++) {
        const int stg = j & 1;
        if (j < jmax) { load_kv(j + 1, stg ^ 1); CP_WAIT1(); }
        else CP_WAIT0();
        __syncthreads();

        const uint32_t KB = sb + stg*FSTG;
        const uint32_t VB = KB + FTILE;

        float sc[8][4];
#pragma unroll
        for (int t = 0; t < 8; t++) { sc[t][0]=0.f; sc[t][1]=0.f; sc[t][2]=0.f; sc[t][3]=0.f; }

        const uint32_t bo = (uint32_t)(((quad>>1)*8 + qi)*144 + (quad&1)*16);
#pragma unroll
        for (int kd = 0; kd < 4; kd++) {
            uint32_t bK[4][4];
#pragma unroll
            for (int p = 0; p < 4; p++)
                ldm_x4(bK[p], KB + bo + p*(16*144) + kd*32);
#pragma unroll
            for (int t = 0; t < 8; t++) {
                const uint32_t* pk = &bK[t>>1][(t&1)*2];
                mma16816h(sc[t], qH[kd], pk);
                mma16816h(sc[t], qL[kd], pk);
            }
        }

        if (j*64 + 63 > qb*128 + w*16) {
#pragma unroll
            for (int t = 0; t < 8; t++) {
                const int colb = j*64 + t*8 + 2*tig;
#pragma unroll
                for (int e = 0; e < 4; e++) {
                    const int col = colb + (e & 1);
                    const int row = row0 + ((e >= 2) ? 8 : 0);
                    sc[t][e] = (col > row) ? -1e30f : sc[t][e] * 0.125f;
                }
            }
        } else {
#pragma unroll
            for (int t = 0; t < 8; t++) {
                sc[t][0] *= 0.125f; sc[t][1] *= 0.125f;
                sc[t][2] *= 0.125f; sc[t][3] *= 0.125f;
            }
        }

        float rm0 = -1e30f, rm1 = -1e30f;
#pragma unroll
        for (int t = 0; t < 8; t++) {
            rm0 = fmaxf(rm0, fmaxf(sc[t][0], sc[t][1]));
            rm1 = fmaxf(rm1, fmaxf(sc[t][2], sc[t][3]));
        }
        rm0 = fmaxf(rm0, __shfl_xor_sync(0xffffffffu, rm0, 1));
        rm0 = fmaxf(rm0, __shfl_xor_sync(0xffffffffu, rm0, 2));
        rm1 = fmaxf(rm1, __shfl_xor_sync(0xffffffffu, rm1, 1));
        rm1 = fmaxf(rm1, __shfl_xor_sync(0xffffffffu, rm1, 2));
        const float mn0 = fmaxf(m0, rm0), mn1 = fmaxf(m1, rm1);
        const float a0 = fexp(m0 - mn0), a1 = fexp(m1 - mn1);
        float s0 = 0.f, s1 = 0.f;
#pragma unroll
        for (int t = 0; t < 8; t++) {
            sc[t][0] = fexp(sc[t][0] - mn0); sc[t][1] = fexp(sc[t][1] - mn0);
            sc[t][2] = fexp(sc[t][2] - mn1); sc[t][3] = fexp(sc[t][3] - mn1);
            s0 += sc[t][0] + sc[t][1];
            s1 += sc[t][2] + sc[t][3];
        }
        s0 += __shfl_xor_sync(0xffffffffu, s0, 1);
        s0 += __shfl_xor_sync(0xffffffffu, s0, 2);
        s1 += __shfl_xor_sync(0xffffffffu, s1, 1);
        s1 += __shfl_xor_sync(0xffffffffu, s1, 2);
        l0 = l0 * a0 + s0; l1 = l1 * a1 + s1;
        m0 = mn0; m1 = mn1;
#pragma unroll
        for (int t = 0; t < 8; t++) {
            o[t][0] *= a0; o[t][1] *= a0; o[t][2] *= a1; o[t][3] *= a1;
        }

        const uint32_t vo = (uint32_t)(((quad&1)*8 + qi)*144 + (quad>>1)*16);
#pragma unroll
        for (int kk = 0; kk < 4; kk++) {
            const int t0 = 2*kk, t1 = 2*kk + 1;
            uint32_t aph[4], apl[4];
            aph[0] = hpack(sc[t0][0], sc[t0][1]);
            aph[1] = hpack(sc[t0][2], sc[t0][3]);
            aph[2] = hpack(sc[t1][0], sc[t1][1]);
            aph[3] = hpack(sc[t1][2], sc[t1][3]);
            apl[0] = hpack(sc[t0][0]-hval(sc[t0][0]), sc[t0][1]-hval(sc[t0][1]));
            apl[1] = hpack(sc[t0][2]-hval(sc[t0][2]), sc[t0][3]-hval(sc[t0][3]));
            apl[2] = hpack(sc[t1][0]-hval(sc[t1][0]), sc[t1][1]-hval(sc[t1][1]));
            apl[3] = hpack(sc[t1][2]-hval(sc[t1][2]), sc[t1][3]-hval(sc[t1][3]));

            uint32_t bV[4][4];
#pragma unroll
            for (int dp = 0; dp < 4; dp++)
                ldm_x4_t(bV[dp], VB + vo + kk*(16*144) + dp*32);
#pragma unroll
            for (int dt = 0; dt < 8; dt++) {
                const uint32_t* pv = &bV[dt>>1][(dt&1)*2];
                mma16816h(o[dt], aph, pv);
                mma16816h(o[dt], apl, pv);
            }
        }
        __syncthreads();
    }

    // epilogue: normalize, write single fp16 attn output
    const float inv0 = 1.0f / l0, inv1 = 1.0f / l1;
    const int b = bh >> 4, h = bh & 15;
    const int s0r = qb*128 + w*16 + g;
    const int s1r = s0r + 8;
#pragma unroll
    for (int t = 0; t < 8; t++) {
        const float x0 = o[t][0]*inv0, x1 = o[t][1]*inv0;
        const float y0 = o[t][2]*inv1, y1 = o[t][3]*inv1;
        const int col = h*64 + t*8 + 2*tig;
        *(uint32_t*)(g_ah16 + ((size_t)(b*PS + s0r))*PD + col) = hpack(x0, x1);
        *(uint32_t*)(g_ah16 + ((size_t)(b*PS + s1r))*PD + col) = hpack(y0, y1);
    }
}

// ---------------------------------------------------------------------------
extern "C" void kernel_launch(void* const* d_in, const int* in_sizes, int n_in,
                              void* d_out, int out_size) {
    const float* x     = (const float*)d_in[0];
    const float* W_qkv = (const float*)d_in[1];
    const float* W_o   = (const float*)d_in[2];
    const int*   tpos  = (const int*)d_in[3];
    float* out = (float*)d_out;

    cudaFuncSetAttribute(flash_mma_kernel,
                         cudaFuncAttributeMaxDynamicSharedMemorySize, FLASH_SMEM);
    cudaFuncSetAttribute(mma_gemm_kernel<0>,
                         cudaFuncAttributeMaxDynamicSharedMemorySize, GEMM_SMEM(0));
    cudaFuncSetAttribute(mma_gemm_kernel<1>,
                         cudaFuncAttributeMaxDynamicSharedMemorySize, GEMM_SMEM(1));

    rope_table_kernel<<<64, 1024>>>(tpos);
    split_x_kernel<<<8192, 256>>>(x);
    cvt_wq_kernel<<<3072, 256>>>(W_qkv);
    cvt_wo_kernel<<<1024, 256>>>(W_o);

    mma_gemm_kernel<0><<<dim3(24, 64), 256, GEMM_SMEM(0)>>>(nullptr);  // QKV + RoPE + cvt
    flash_mma_kernel<<<dim3(16, 64), 256, FLASH_SMEM>>>();
    mma_gemm_kernel<1><<<dim3(8, 64), 256, GEMM_SMEM(1)>>>(out);       // out proj
}

// round 15
// speedup vs baseline: 2.4656x; 1.4253x over previous
#include <cuda_runtime.h>
#include <cuda_fp16.h>
#include <math.h>
#include <stdint.h>

// Problem constants
#define PB 4
#define PS 2048
#define PD 1024
#define PH 16
#define PDH 64

// ---------------------------------------------------------------------------
// Scratch (device globals — no allocations allowed)
// ---------------------------------------------------------------------------
__device__ float g_cos[PS*32];
__device__ float g_sin[PS*32];

__device__ __half g_x16[8192*1024];
__device__ __half g_wq16[3072*1024];
__device__ __half g_wo16[1024*1024];
__device__ __half g_ah16[8192*1024];                  // attn out (single fp16)

// q/k/v fp16 (all single) for flash, layout [b*H+h][s][dh]
__device__ __half gq16[PB*PH*PS*PDH];
__device__ __half gk16[PB*PH*PS*PDH];
__device__ __half gv16[PB*PH*PS*PDH];

// ---------------------------------------------------------------------------
// Portable PTX helpers
// ---------------------------------------------------------------------------
__device__ __forceinline__ uint32_t smem_u32(const void* p) {
    uint32_t a;
    asm("{ .reg .u64 t; cvta.to.shared.u64 t, %1; cvt.u32.u64 %0, t; }"
        : "=r"(a) : "l"(p));
    return a;
}

__device__ __forceinline__ void cp16(uint32_t saddr, const void* gaddr) {
    asm volatile("cp.async.cg.shared.global [%0], [%1], 16;"
                 :: "r"(saddr), "l"(gaddr) : "memory");
}
#define CP_COMMIT() asm volatile("cp.async.commit_group;" ::: "memory")
#define CP_WAIT0()  asm volatile("cp.async.wait_group 0;" ::: "memory")
#define CP_WAIT1()  asm volatile("cp.async.wait_group 1;" ::: "memory")
#define CP_WAIT2()  asm volatile("cp.async.wait_group 2;" ::: "memory")

__device__ __forceinline__ void ldm_x4(uint32_t* r, uint32_t addr) {
    asm volatile("ldmatrix.sync.aligned.m8n8.x4.shared.b16 {%0,%1,%2,%3}, [%4];"
        : "=r"(r[0]), "=r"(r[1]), "=r"(r[2]), "=r"(r[3]) : "r"(addr));
}
__device__ __forceinline__ void ldm_x4_t(uint32_t* r, uint32_t addr) {
    asm volatile("ldmatrix.sync.aligned.m8n8.x4.trans.shared.b16 {%0,%1,%2,%3}, [%4];"
        : "=r"(r[0]), "=r"(r[1]), "=r"(r[2]), "=r"(r[3]) : "r"(addr));
}

__device__ __forceinline__ void mma16816h(float* d, const uint32_t* a, const uint32_t* b) {
    asm volatile(
        "mma.sync.aligned.m16n8k16.row.col.f32.f16.f16.f32 "
        "{%0,%1,%2,%3}, {%4,%5,%6,%7}, {%8,%9}, {%0,%1,%2,%3};"
        : "+f"(d[0]), "+f"(d[1]), "+f"(d[2]), "+f"(d[3])
        : "r"(a[0]), "r"(a[1]), "r"(a[2]), "r"(a[3]), "r"(b[0]), "r"(b[1]));
}

__device__ __forceinline__ uint32_t hpack(float a, float b) {
    __half2 h = __floats2half2_rn(a, b);
    return *(uint32_t*)&h;
}

// Fast exp on FMA pipe (valid for x <= ~0, clamps at -87)
__device__ __forceinline__ float fexp(float x) {
    float xc = fmaxf(x, -87.0f);
    float t  = fmaf(xc, 1.4426950408889634f, 12582912.0f);
    float n  = t - 12582912.0f;
    float r  = fmaf(n, -0.6931471805599453f, xc);
    float p  = 8.3333333e-3f;
    p = fmaf(p, r, 4.1666667e-2f);
    p = fmaf(p, r, 1.6666667e-1f);
    p = fmaf(p, r, 5.0e-1f);
    p = fmaf(p, r, 1.0f);
    p = fmaf(p, r, 1.0f);
    float s = __int_as_float((__float_as_int(t) << 23) + 0x3f800000);
    return p * s;
}

// ---------------------------------------------------------------------------
// RoPE table (fp64 for fidelity)
// ---------------------------------------------------------------------------
__global__ void rope_table_kernel(const int* __restrict__ pos) {
    int idx = blockIdx.x * blockDim.x + threadIdx.x;   // 65536
    int s = idx >> 5;
    int i = idx & 31;
    double p = (double)pos[s];
    double inv = exp(-((double)(2 * i) / 64.0) * log(10000.0));
    double a = p * inv;
    g_cos[idx] = (float)cos(a);
    g_sin[idx] = (float)sin(a);
}

// ---------------------------------------------------------------------------
// Conversions (fp32 -> single fp16)
// ---------------------------------------------------------------------------
__global__ void cvt_x_kernel(const float* __restrict__ x) {
    int i = blockIdx.x * blockDim.x + threadIdx.x;
    float4 v = ((const float4*)x)[i];
    ((uint32_t*)g_x16)[i*2]   = hpack(v.x, v.y);
    ((uint32_t*)g_x16)[i*2+1] = hpack(v.z, v.w);
}
__global__ void cvt_wq_kernel(const float* __restrict__ w) {
    int i = blockIdx.x * blockDim.x + threadIdx.x;
    float4 v = ((const float4*)w)[i];
    ((uint32_t*)g_wq16)[i*2]   = hpack(v.x, v.y);
    ((uint32_t*)g_wq16)[i*2+1] = hpack(v.z, v.w);
}
__global__ void cvt_wo_kernel(const float* __restrict__ w) {
    int i = blockIdx.x * blockDim.x + threadIdx.x;
    float4 v = ((const float4*)w)[i];
    ((uint32_t*)g_wo16)[i*2]   = hpack(v.x, v.y);
    ((uint32_t*)g_wo16)[i*2+1] = hpack(v.z, v.w);
}

// ---------------------------------------------------------------------------
// fp16 mma GEMM (1-term): 128x128 CTA tile, BK=32, 256 threads, warp 64x32,
// 3-stage cp.async pipeline, 2 tiles/stage (A, B) = 61440 B smem.
// MODE 0: A=x, B=W_qkv. Epilogue RoPE; q,k,v -> fp16 single.
// MODE 1: A=attn fp16, B=W_o. Epilogue fp32 store.
// ---------------------------------------------------------------------------
#define LDT 40
#define TILE_B (128*LDT*2)                 // 10240 B
#define STAGE_B (2*TILE_B)                 // 20480 B
#define GEMM_SMEM (3*STAGE_B)              // 61440 B

template<int MODE>
__global__ __launch_bounds__(256)
void mma_gemm_kernel(float* __restrict__ Cout)
{
    const __half *Ap, *Bp;
    if (MODE == 0) { Ap = g_x16;  Bp = g_wq16; }
    else           { Ap = g_ah16; Bp = g_wo16; }

    extern __shared__ char dsm[];
    const uint32_t sBase = smem_u32(dsm);

    const int tid = threadIdx.x;
    const int n0 = blockIdx.x * 128;
    const int m0 = blockIdx.y * 128;
    const int lane = tid & 31, w = tid >> 5;
    const int wm = w >> 2, wn = w & 3;

    const int lr = tid >> 1, lh = tid & 1;
    const __half* gA = Ap + (size_t)(m0 + lr) * 1024 + lh * 16;
    const __half* gB = Bp + (size_t)(n0 + lr) * 1024 + lh * 16;
    const uint32_t sOff = (uint32_t)((lr * LDT + lh * 16) * 2);

    const int quad = lane >> 3, qi = lane & 7;
    const uint32_t aoff = (uint32_t)(((wm*64 + (quad&1)*8 + qi) * LDT + (quad>>1)*8) * 2);
    const uint32_t boff = (uint32_t)(((wn*32 + (quad>>1)*8 + qi) * LDT + (quad&1)*8) * 2);

    float acc[4][4][4];
#pragma unroll
    for (int a = 0; a < 4; a++)
#pragma unroll
        for (int b = 0; b < 4; b++)
#pragma unroll
            for (int c = 0; c < 4; c++) acc[a][b][c] = 0.0f;

    auto load_stage = [&](int kt, int stg) {
        const int kb = kt * 32;
        const uint32_t s0 = sBase + stg * STAGE_B + sOff;
        cp16(s0,            gA + kb);  cp16(s0 + 16,          gA + kb + 8);
        cp16(s0 + TILE_B,   gB + kb);  cp16(s0 + TILE_B + 16, gB + kb + 8);
        CP_COMMIT();
    };

    load_stage(0, 0);
    load_stage(1, 1);

    for (int kt = 0; kt < 32; kt++) {
        const int stg = kt % 3;
        if (kt + 2 < 32) { load_stage(kt + 2, (kt + 2) % 3); CP_WAIT2(); }
        else if (kt + 1 < 32) CP_WAIT1();
        else CP_WAIT0();
        __syncthreads();

        const uint32_t sAB = sBase + stg * STAGE_B;
        const uint32_t sBB = sAB + TILE_B;

#pragma unroll
        for (int ks = 0; ks < 2; ks++) {
            const uint32_t kso = ks * 32;
            uint32_t aA[4][4], bB[2][4];
#pragma unroll
            for (int mt = 0; mt < 4; mt++)
                ldm_x4(aA[mt], sAB + aoff + mt * (16*LDT*2) + kso);
#pragma unroll
            for (int np = 0; np < 2; np++)
                ldm_x4(bB[np], sBB + boff + np * (16*LDT*2) + kso);
#pragma unroll
            for (int mt = 0; mt < 4; mt++)
#pragma unroll
                for (int nt = 0; nt < 4; nt++) {
                    const uint32_t* pb = &bB[nt >> 1][(nt & 1) * 2];
                    mma16816h(acc[mt][nt], aA[mt], pb);
                }
        }
        __syncthreads();
    }

    const int g = lane >> 2, tig = lane & 3;
    if (MODE == 0) {
        const int kmat = n0 >> 10;                   // 0=q 1=k 2=v
        __half* dst = (kmat == 0) ? gq16 : ((kmat == 1) ? gk16 : gv16);
#pragma unroll
        for (int mt = 0; mt < 4; mt++)
#pragma unroll
            for (int hh = 0; hh < 2; hh++) {
                const int m = m0 + wm*64 + mt*16 + hh*8 + g;
                const int b = m >> 11, s = m & 2047;
#pragma unroll
                for (int nt = 0; nt < 4; nt++) {
                    const int colg = n0 + wn*32 + nt*8 + 2*tig;
                    const int h = (colg >> 6) & 15;
                    const int cc = colg & 63;
                    const float v0 = acc[mt][nt][hh*2];
                    const float v1 = acc[mt][nt][hh*2 + 1];
                    float rx, ry;
                    if (kmat < 2) {
                        const int pi = (s << 5) + (cc >> 1);
                        const float c_ = g_cos[pi], s_ = g_sin[pi];
                        rx = v0 * c_ - v1 * s_;
                        ry = v0 * s_ + v1 * c_;
                    } else {
                        rx = v0; ry = v1;
                    }
                    size_t idx = ((size_t)((b*PH + h)*PS + s))*PDH + cc;
                    *(uint32_t*)(dst + idx) = hpack(rx, ry);
                }
            }
    } else {
#pragma unroll
        for (int mt = 0; mt < 4; mt++)
#pragma unroll
            for (int hh = 0; hh < 2; hh++) {
                const int m = m0 + wm*64 + mt*16 + hh*8 + g;
#pragma unroll
                for (int nt = 0; nt < 4; nt++) {
                    const int colg = n0 + wn*32 + nt*8 + 2*tig;
                    float2 r;
                    r.x = acc[mt][nt][hh*2];
                    r.y = acc[mt][nt][hh*2 + 1];
                    *(float2*)(Cout + (size_t)m * 1024 + colg) = r;
                }
            }
    }
}

// ---------------------------------------------------------------------------
// Tensor-core flash attention, fp16 1-term.
// q-tile 128 (8 warps x m16), k-tile 64.
// Scores: Q*K (1 mma/tile, fp32 acc); softmax in registers;
// PV: P*V (P single fp16, V via ldmatrix.trans).
// K/V double-buffered cp.async; Q staged once -> registers.
// Output single fp16 to g_ah16 [b][s][h*64+c].
// ---------------------------------------------------------------------------
#define FTILE 9216            // 64 rows * 144 B (72-fp16 stride)
#define FSTG  (2*FTILE)       // K, V = 18432
#define FLASH_SMEM (2*FSTG)   // 36864

__global__ __launch_bounds__(256) void flash_mma_kernel() {
    extern __shared__ char fsm[];
    const uint32_t sb = smem_u32(fsm);
    const int tid = threadIdx.x, lane = tid & 31, w = tid >> 5;
    const int qb = 15 - (int)blockIdx.x;       // heavy CTAs first
    const int bh = blockIdx.y;
    const int quad = lane >> 3, qi = lane & 7;
    const int g = lane >> 2, tig = lane & 3;

    const size_t bhoff = (size_t)bh * PS * PDH;
    const __half* K0 = gk16 + bhoff;
    const __half* V0 = gv16 + bhoff;

    // ---- stage Q (128 rows x 144B) into stage-0 area, ldmatrix -> regs ----
    {
        const int row = tid >> 1, hf = tid & 1;
        const __half* src = gq16 + bhoff + (size_t)(qb*128 + row)*PDH + hf*32;
        uint32_t dst = sb + (uint32_t)row*144 + hf*64;
#pragma unroll
        for (int u = 0; u < 4; u++) cp16(dst + u*16, (const char*)src + u*16);
        CP_COMMIT();
    }
    CP_WAIT0();
    __syncthreads();

    uint32_t qA[4][4];
    {
        const uint32_t ao = (uint32_t)((w*16 + (quad&1)*8 + qi)*144 + (quad>>1)*16);
#pragma unroll
        for (int kd = 0; kd < 4; kd++)
            ldm_x4(qA[kd], sb + ao + kd*32);
    }
    __syncthreads();   // staging area free for K/V

    const int jmax = 2*qb + 1;

    auto load_kv = [&](int j, int stg) {
        const int t = tid >> 7;            // 0 K, 1 V
        const int rr = tid & 127;
        const int row = rr >> 1, hf = rr & 1;
        const __half* src = (t == 0 ? K0 : V0) + (size_t)(j*64 + row)*PDH + hf*32;
        uint32_t dst = sb + stg*FSTG + t*FTILE + (uint32_t)row*144 + hf*64;
#pragma unroll
        for (int u = 0; u < 4; u++) cp16(dst + u*16, (const char*)src + u*16);
        CP_COMMIT();
    };

    float o[8][4];
#pragma unroll
    for (int t = 0; t < 8; t++) { o[t][0]=0.f; o[t][1]=0.f; o[t][2]=0.f; o[t][3]=0.f; }
    float m0 = -1e30f, m1 = -1e30f, l0 = 0.f, l1 = 0.f;
    const int row0 = qb*128 + w*16 + g;

    load_kv(0, 0);

    for (int j = 0; j <= jmax; j++) {
        const int stg = j & 1;
        if (j < jmax) { load_kv(j + 1, stg ^ 1); CP_WAIT1(); }
        else CP_WAIT0();
        __syncthreads();

        const uint32_t KB = sb + stg*FSTG;
        const uint32_t VB = KB + FTILE;

        // ---- QK^T (1 mma per tile) ----
        float sc[8][4];
#pragma unroll
        for (int t = 0; t < 8; t++) { sc[t][0]=0.f; sc[t][1]=0.f; sc[t][2]=0.f; sc[t][3]=0.f; }

        const uint32_t bo = (uint32_t)(((quad>>1)*8 + qi)*144 + (quad&1)*16);
#pragma unroll
        for (int kd = 0; kd < 4; kd++) {
            uint32_t bK[4][4];
#pragma unroll
            for (int p = 0; p < 4; p++)
                ldm_x4(bK[p], KB + bo + p*(16*144) + kd*32);
#pragma unroll
            for (int t = 0; t < 8; t++)
                mma16816h(sc[t], qA[kd], &bK[t>>1][(t&1)*2]);
        }

        // ---- scale + causal mask ----
        if (j*64 + 63 > qb*128 + w*16) {
#pragma unroll
            for (int t = 0; t < 8; t++) {
                const int colb = j*64 + t*8 + 2*tig;
#pragma unroll
                for (int e = 0; e < 4; e++) {
                    const int col = colb + (e & 1);
                    const int row = row0 + ((e >= 2) ? 8 : 0);
                    sc[t][e] = (col > row) ? -1e30f : sc[t][e] * 0.125f;
                }
            }
        } else {
#pragma unroll
            for (int t = 0; t < 8; t++) {
                sc[t][0] *= 0.125f; sc[t][1] *= 0.125f;
                sc[t][2] *= 0.125f; sc[t][3] *= 0.125f;
            }
        }

        // ---- online softmax (rows g and g+8) ----
        float rm0 = -1e30f, rm1 = -1e30f;
#pragma unroll
        for (int t = 0; t < 8; t++) {
            rm0 = fmaxf(rm0, fmaxf(sc[t][0], sc[t][1]));
            rm1 = fmaxf(rm1, fmaxf(sc[t][2], sc[t][3]));
        }
        rm0 = fmaxf(rm0, __shfl_xor_sync(0xffffffffu, rm0, 1));
        rm0 = fmaxf(rm0, __shfl_xor_sync(0xffffffffu, rm0, 2));
        rm1 = fmaxf(rm1, __shfl_xor_sync(0xffffffffu, rm1, 1));
        rm1 = fmaxf(rm1, __shfl_xor_sync(0xffffffffu, rm1, 2));
        const float mn0 = fmaxf(m0, rm0), mn1 = fmaxf(m1, rm1);
        const float a0 = fexp(m0 - mn0), a1 = fexp(m1 - mn1);
        float s0 = 0.f, s1 = 0.f;
#pragma unroll
        for (int t = 0; t < 8; t++) {
            sc[t][0] = fexp(sc[t][0] - mn0); sc[t][1] = fexp(sc[t][1] - mn0);
            sc[t][2] = fexp(sc[t][2] - mn1); sc[t][3] = fexp(sc[t][3] - mn1);
            s0 += sc[t][0] + sc[t][1];
            s1 += sc[t][2] + sc[t][3];
        }
        s0 += __shfl_xor_sync(0xffffffffu, s0, 1);
        s0 += __shfl_xor_sync(0xffffffffu, s0, 2);
        s1 += __shfl_xor_sync(0xffffffffu, s1, 1);
        s1 += __shfl_xor_sync(0xffffffffu, s1, 2);
        l0 = l0 * a0 + s0; l1 = l1 * a1 + s1;
        m0 = mn0; m1 = mn1;
#pragma unroll
        for (int t = 0; t < 8; t++) {
            o[t][0] *= a0; o[t][1] *= a0; o[t][2] *= a1; o[t][3] *= a1;
        }

        // ---- PV: P single fp16, V via ldmatrix.trans ----
        const uint32_t vo = (uint32_t)(((quad&1)*8 + qi)*144 + (quad>>1)*16);
#pragma unroll
        for (int kk = 0; kk < 4; kk++) {
            const int t0 = 2*kk, t1 = 2*kk + 1;
            uint32_t ap[4];
            ap[0] = hpack(sc[t0][0], sc[t0][1]);
            ap[1] = hpack(sc[t0][2], sc[t0][3]);
            ap[2] = hpack(sc[t1][0], sc[t1][1]);
            ap[3] = hpack(sc[t1][2], sc[t1][3]);

            uint32_t bV[4][4];
#pragma unroll
            for (int dp = 0; dp < 4; dp++)
                ldm_x4_t(bV[dp], VB + vo + kk*(16*144) + dp*32);
#pragma unroll
            for (int dt = 0; dt < 8; dt++)
                mma16816h(o[dt], ap, &bV[dt>>1][(dt&1)*2]);
        }
        __syncthreads();
    }

    // ---- epilogue: normalize, write single fp16 attn output ----
    const float inv0 = 1.0f / l0, inv1 = 1.0f / l1;
    const int b = bh >> 4, h = bh & 15;
    const int s0r = qb*128 + w*16 + g;
    const int s1r = s0r + 8;
#pragma unroll
    for (int t = 0; t < 8; t++) {
        const float x0 = o[t][0]*inv0, x1 = o[t][1]*inv0;
        const float y0 = o[t][2]*inv1, y1 = o[t][3]*inv1;
        const int col = h*64 + t*8 + 2*tig;
        *(uint32_t*)(g_ah16 + ((size_t)(b*PS + s0r))*PD + col) = hpack(x0, x1);
        *(uint32_t*)(g_ah16 + ((size_t)(b*PS + s1r))*PD + col) = hpack(y0, y1);
    }
}

// ---------------------------------------------------------------------------
extern "C" void kernel_launch(void* const* d_in, const int* in_sizes, int n_in,
                              void* d_out, int out_size) {
    const float* x     = (const float*)d_in[0];
    const float* W_qkv = (const float*)d_in[1];
    const float* W_o   = (const float*)d_in[2];
    const int*   tpos  = (const int*)d_in[3];
    float* out = (float*)d_out;

    cudaFuncSetAttribute(flash_mma_kernel,
                         cudaFuncAttributeMaxDynamicSharedMemorySize, FLASH_SMEM);
    cudaFuncSetAttribute(mma_gemm_kernel<0>,
                         cudaFuncAttributeMaxDynamicSharedMemorySize, GEMM_SMEM);
    cudaFuncSetAttribute(mma_gemm_kernel<1>,
                         cudaFuncAttributeMaxDynamicSharedMemorySize, GEMM_SMEM);

    rope_table_kernel<<<64, 1024>>>(tpos);
    cvt_x_kernel<<<8192, 256>>>(x);
    cvt_wq_kernel<<<3072, 256>>>(W_qkv);
    cvt_wo_kernel<<<1024, 256>>>(W_o);

    mma_gemm_kernel<0><<<dim3(24, 64), 256, GEMM_SMEM>>>(nullptr);   // QKV + RoPE
    flash_mma_kernel<<<dim3(16, 64), 256, FLASH_SMEM>>>();
    mma_gemm_kernel<1><<<dim3(8, 64), 256, GEMM_SMEM>>>(out);        // out proj
}

// round 17
// speedup vs baseline: 2.5083x; 1.0173x over previous
#include <cuda_runtime.h>
#include <cuda_fp16.h>
#include <math.h>
#include <stdint.h>

// Problem constants
#define PB 4
#define PS 2048
#define PD 1024
#define PH 16
#define PDH 64

// ---------------------------------------------------------------------------
// Scratch (device globals — no allocations allowed)
// ---------------------------------------------------------------------------
__device__ float g_cos[PS*32];
__device__ float g_sin[PS*32];

__device__ __half g_x16[8192*1024];
__device__ __half g_wq16[3072*1024];
__device__ __half g_wo16[1024*1024];
__device__ __half g_ah16[8192*1024];                  // attn out (single fp16)

// q/k/v fp16 (q pre-scaled by 0.125), layout [b*H+h][s][dh]
__device__ __half gq16[PB*PH*PS*PDH];
__device__ __half gk16[PB*PH*PS*PDH];
__device__ __half gv16[PB*PH*PS*PDH];

// ---------------------------------------------------------------------------
// Portable PTX helpers
// ---------------------------------------------------------------------------
__device__ __forceinline__ uint32_t smem_u32(const void* p) {
    uint32_t a;
    asm("{ .reg .u64 t; cvta.to.shared.u64 t, %1; cvt.u32.u64 %0, t; }"
        : "=r"(a) : "l"(p));
    return a;
}

__device__ __forceinline__ void cp16(uint32_t saddr, const void* gaddr) {
    asm volatile("cp.async.cg.shared.global [%0], [%1], 16;"
                 :: "r"(saddr), "l"(gaddr) : "memory");
}
#define CP_COMMIT() asm volatile("cp.async.commit_group;" ::: "memory")
#define CP_WAIT0()  asm volatile("cp.async.wait_group 0;" ::: "memory")
#define CP_WAIT1()  asm volatile("cp.async.wait_group 1;" ::: "memory")
#define CP_WAIT2()  asm volatile("cp.async.wait_group 2;" ::: "memory")

__device__ __forceinline__ void ldm_x4(uint32_t* r, uint32_t addr) {
    asm volatile("ldmatrix.sync.aligned.m8n8.x4.shared.b16 {%0,%1,%2,%3}, [%4];"
        : "=r"(r[0]), "=r"(r[1]), "=r"(r[2]), "=r"(r[3]) : "r"(addr));
}
__device__ __forceinline__ void ldm_x4_t(uint32_t* r, uint32_t addr) {
    asm volatile("ldmatrix.sync.aligned.m8n8.x4.trans.shared.b16 {%0,%1,%2,%3}, [%4];"
        : "=r"(r[0]), "=r"(r[1]), "=r"(r[2]), "=r"(r[3]) : "r"(addr));
}

// fp16 inputs, fp32 acc
__device__ __forceinline__ void mma16816h(float* d, const uint32_t* a, const uint32_t* b) {
    asm volatile(
        "mma.sync.aligned.m16n8k16.row.col.f32.f16.f16.f32 "
        "{%0,%1,%2,%3}, {%4,%5,%6,%7}, {%8,%9}, {%0,%1,%2,%3};"
        : "+f"(d[0]), "+f"(d[1]), "+f"(d[2]), "+f"(d[3])
        : "r"(a[0]), "r"(a[1]), "r"(a[2]), "r"(a[3]), "r"(b[0]), "r"(b[1]));
}
// fp16 inputs, fp16 acc (2 regs = 4 halves; layout matches f32 acc order)
__device__ __forceinline__ void mma16816hh(uint32_t* d, const uint32_t* a, const uint32_t* b) {
    asm volatile(
        "mma.sync.aligned.m16n8k16.row.col.f16.f16.f16.f16 "
        "{%0,%1}, {%2,%3,%4,%5}, {%6,%7}, {%0,%1};"
        : "+r"(d[0]), "+r"(d[1])
        : "r"(a[0]), "r"(a[1]), "r"(a[2]), "r"(a[3]), "r"(b[0]), "r"(b[1]));
}

__device__ __forceinline__ uint32_t hpack(float a, float b) {
    __half2 h = __floats2half2_rn(a, b);
    return *(uint32_t*)&h;
}

// Fast exp on FMA pipe (valid for x <= ~0, clamps at -87)
__device__ __forceinline__ float fexp(float x) {
    float xc = fmaxf(x, -87.0f);
    float t  = fmaf(xc, 1.4426950408889634f, 12582912.0f);
    float n  = t - 12582912.0f;
    float r  = fmaf(n, -0.6931471805599453f, xc);
    float p  = 8.3333333e-3f;
    p = fmaf(p, r, 4.1666667e-2f);
    p = fmaf(p, r, 1.6666667e-1f);
    p = fmaf(p, r, 5.0e-1f);
    p = fmaf(p, r, 1.0f);
    p = fmaf(p, r, 1.0f);
    float s = __int_as_float((__float_as_int(t) << 23) + 0x3f800000);
    return p * s;
}

// ---------------------------------------------------------------------------
// Fused prep: cvt x/W_qkv/W_o to fp16 + RoPE table, one launch.
// Segments (float4 units): x 2097152 | wq 786432 | wo 262144 | rope 65536.
// ---------------------------------------------------------------------------
#define PREP_X  2097152
#define PREP_WQ (PREP_X + 786432)
#define PREP_WO (PREP_WQ + 262144)
#define PREP_N  (PREP_WO + 65536)

__global__ void prep_kernel(const float* __restrict__ x,
                            const float* __restrict__ wq,
                            const float* __restrict__ wo,
                            const int* __restrict__ pos) {
    int idx = blockIdx.x * blockDim.x + threadIdx.x;
    if (idx < PREP_X) {
        float4 v = ((const float4*)x)[idx];
        ((uint32_t*)g_x16)[idx*2]   = hpack(v.x, v.y);
        ((uint32_t*)g_x16)[idx*2+1] = hpack(v.z, v.w);
    } else if (idx < PREP_WQ) {
        int i = idx - PREP_X;
        float4 v = ((const float4*)wq)[i];
        ((uint32_t*)g_wq16)[i*2]   = hpack(v.x, v.y);
        ((uint32_t*)g_wq16)[i*2+1] = hpack(v.z, v.w);
    } else if (idx < PREP_WO) {
        int i = idx - PREP_WQ;
        float4 v = ((const float4*)wo)[i];
        ((uint32_t*)g_wo16)[i*2]   = hpack(v.x, v.y);
        ((uint32_t*)g_wo16)[i*2+1] = hpack(v.z, v.w);
    } else if (idx < PREP_N) {
        int i = idx - PREP_WO;       // 0..65535 = s*32 + f
        int s = i >> 5;
        int f = i & 31;
        double p = (double)pos[s];
        double inv = exp(-((double)(2 * f) / 64.0) * log(10000.0));
        double a = p * inv;
        g_cos[i] = (float)cos(a);
        g_sin[i] = (float)sin(a);
    }
}

// ---------------------------------------------------------------------------
// fp16 mma GEMM (1-term, f32 acc): 128x128 CTA, BK=32, 256 thr, warp 64x32,
// 3-stage cp.async pipeline, 2 tiles/stage = 61440 B smem.
// MODE 0: A=x, B=W_qkv. Epilogue RoPE; q scaled by 0.125; q,k,v fp16.
// MODE 1: A=attn fp16, B=W_o. Epilogue fp32 store.
// ---------------------------------------------------------------------------
#define LDT 40
#define TILE_B (128*LDT*2)                 // 10240 B
#define STAGE_B (2*TILE_B)                 // 20480 B
#define GEMM_SMEM (3*STAGE_B)              // 61440 B

template<int MODE>
__global__ __launch_bounds__(256)
void mma_gemm_kernel(float* __restrict__ Cout)
{
    const __half *Ap, *Bp;
    if (MODE == 0) { Ap = g_x16;  Bp = g_wq16; }
    else           { Ap = g_ah16; Bp = g_wo16; }

    extern __shared__ char dsm[];
    const uint32_t sBase = smem_u32(dsm);

    const int tid = threadIdx.x;
    const int n0 = blockIdx.x * 128;
    const int m0 = blockIdx.y * 128;
    const int lane = tid & 31, w = tid >> 5;
    const int wm = w >> 2, wn = w & 3;

    const int lr = tid >> 1, lh = tid & 1;
    const __half* gA = Ap + (size_t)(m0 + lr) * 1024 + lh * 16;
    const __half* gB = Bp + (size_t)(n0 + lr) * 1024 + lh * 16;
    const uint32_t sOff = (uint32_t)((lr * LDT + lh * 16) * 2);

    const int quad = lane >> 3, qi = lane & 7;
    const uint32_t aoff = (uint32_t)(((wm*64 + (quad&1)*8 + qi) * LDT + (quad>>1)*8) * 2);
    const uint32_t boff = (uint32_t)(((wn*32 + (quad>>1)*8 + qi) * LDT + (quad&1)*8) * 2);

    float acc[4][4][4];
#pragma unroll
    for (int a = 0; a < 4; a++)
#pragma unroll
        for (int b = 0; b < 4; b++)
#pragma unroll
            for (int c = 0; c < 4; c++) acc[a][b][c] = 0.0f;

    auto load_stage = [&](int kt, int stg) {
        const int kb = kt * 32;
        const uint32_t s0 = sBase + stg * STAGE_B + sOff;
        cp16(s0,            gA + kb);  cp16(s0 + 16,          gA + kb + 8);
        cp16(s0 + TILE_B,   gB + kb);  cp16(s0 + TILE_B + 16, gB + kb + 8);
        CP_COMMIT();
    };

    load_stage(0, 0);
    load_stage(1, 1);

    for (int kt = 0; kt < 32; kt++) {
        const int stg = kt % 3;
        if (kt + 2 < 32) { load_stage(kt + 2, (kt + 2) % 3); CP_WAIT2(); }
        else if (kt + 1 < 32) CP_WAIT1();
        else CP_WAIT0();
        __syncthreads();

        const uint32_t sAB = sBase + stg * STAGE_B;
        const uint32_t sBB = sAB + TILE_B;

#pragma unroll
        for (int ks = 0; ks < 2; ks++) {
            const uint32_t kso = ks * 32;
            uint32_t aA[4][4], bB[2][4];
#pragma unroll
            for (int mt = 0; mt < 4; mt++)
                ldm_x4(aA[mt], sAB + aoff + mt * (16*LDT*2) + kso);
#pragma unroll
            for (int np = 0; np < 2; np++)
                ldm_x4(bB[np], sBB + boff + np * (16*LDT*2) + kso);
#pragma unroll
            for (int mt = 0; mt < 4; mt++)
#pragma unroll
                for (int nt = 0; nt < 4; nt++) {
                    const uint32_t* pb = &bB[nt >> 1][(nt & 1) * 2];
                    mma16816h(acc[mt][nt], aA[mt], pb);
                }
        }
        __syncthreads();
    }

    const int g = lane >> 2, tig = lane & 3;
    if (MODE == 0) {
        const int kmat = n0 >> 10;                   // 0=q 1=k 2=v
        __half* dst = (kmat == 0) ? gq16 : ((kmat == 1) ? gk16 : gv16);
        const float oscale = (kmat == 0) ? 0.125f : 1.0f;   // fold 1/sqrt(dh) into q
#pragma unroll
        for (int mt = 0; mt < 4; mt++)
#pragma unroll
            for (int hh = 0; hh < 2; hh++) {
                const int m = m0 + wm*64 + mt*16 + hh*8 + g;
                const int b = m >> 11, s = m & 2047;
#pragma unroll
                for (int nt = 0; nt < 4; nt++) {
                    const int colg = n0 + wn*32 + nt*8 + 2*tig;
                    const int h = (colg >> 6) & 15;
                    const int cc = colg & 63;
                    const float v0 = acc[mt][nt][hh*2];
                    const float v1 = acc[mt][nt][hh*2 + 1];
                    float rx, ry;
                    if (kmat < 2) {
                        const int pi = (s << 5) + (cc >> 1);
                        const float c_ = g_cos[pi], s_ = g_sin[pi];
                        rx = (v0 * c_ - v1 * s_) * oscale;
                        ry = (v0 * s_ + v1 * c_) * oscale;
                    } else {
                        rx = v0; ry = v1;
                    }
                    size_t idx = ((size_t)((b*PH + h)*PS + s))*PDH + cc;
                    *(uint32_t*)(dst + idx) = hpack(rx, ry);
                }
            }
    } else {
#pragma unroll
        for (int mt = 0; mt < 4; mt++)
#pragma unroll
            for (int hh = 0; hh < 2; hh++) {
                const int m = m0 + wm*64 + mt*16 + hh*8 + g;
#pragma unroll
                for (int nt = 0; nt < 4; nt++) {
                    const int colg = n0 + wn*32 + nt*8 + 2*tig;
                    float2 r;
                    r.x = acc[mt][nt][hh*2];
                    r.y = acc[mt][nt][hh*2 + 1];
                    *(float2*)(Cout + (size_t)m * 1024 + colg) = r;
                }
            }
    }
}

// ---------------------------------------------------------------------------
// Tensor-core flash attention, fp16 1-term.
// QK with fp16 ACCUMULATORS (rate experiment); PV f32 acc.
// Scale pre-folded into q. Fully-masked warp-tiles skipped.
// ---------------------------------------------------------------------------
#define FTILE 9216            // 64 rows * 144 B (72-fp16 stride)
#define FSTG  (2*FTILE)       // K, V = 18432
#define FLASH_SMEM (2*FSTG)   // 36864

__global__ __launch_bounds__(256) void flash_mma_kernel() {
    extern __shared__ char fsm[];
    const uint32_t sb = smem_u32(fsm);
    const int tid = threadIdx.x, lane = tid & 31, w = tid >> 5;
    const int qb = 15 - (int)blockIdx.x;       // heavy CTAs first
    const int bh = blockIdx.y;
    const int quad = lane >> 3, qi = lane & 7;
    const int g = lane >> 2, tig = lane & 3;

    const size_t bhoff = (size_t)bh * PS * PDH;
    const __half* K0 = gk16 + bhoff;
    const __half* V0 = gv16 + bhoff;

    // ---- stage Q, ldmatrix -> regs ----
    {
        const int row = tid >> 1, hf = tid & 1;
        const __half* src = gq16 + bhoff + (size_t)(qb*128 + row)*PDH + hf*32;
        uint32_t dst = sb + (uint32_t)row*144 + hf*64;
#pragma unroll
        for (int u = 0; u < 4; u++) cp16(dst + u*16, (const char*)src + u*16);
        CP_COMMIT();
    }
    CP_WAIT0();
    __syncthreads();

    uint32_t qA[4][4];
    {
        const uint32_t ao = (uint32_t)((w*16 + (quad&1)*8 + qi)*144 + (quad>>1)*16);
#pragma unroll
        for (int kd = 0; kd < 4; kd++)
            ldm_x4(qA[kd], sb + ao + kd*32);
    }
    __syncthreads();

    const int jmax = 2*qb + 1;

    auto load_kv = [&](int j, int stg) {
        const int t = tid >> 7;            // 0 K, 1 V
        const int rr = tid & 127;
        const int row = rr >> 1, hf = rr & 1;
        const __half* src = (t == 0 ? K0 : V0) + (size_t)(j*64 + row)*PDH + hf*32;
        uint32_t dst = sb + stg*FSTG + t*FTILE + (uint32_t)row*144 + hf*64;
#pragma unroll
        for (int u = 0; u < 4; u++) cp16(dst + u*16, (const char*)src + u*16);
        CP_COMMIT();
    };

    float o[8][4];
#pragma unroll
    for (int t = 0; t < 8; t++) { o[t][0]=0.f; o[t][1]=0.f; o[t][2]=0.f; o[t][3]=0.f; }
    float m0 = -1e30f, m1 = -1e30f, l0 = 0.f, l1 = 0.f;
    const int row0 = qb*128 + w*16 + g;

    load_kv(0, 0);

    for (int j = 0; j <= jmax; j++) {
        const int stg = j & 1;
        if (j < jmax) { load_kv(j + 1, stg ^ 1); CP_WAIT1(); }
        else CP_WAIT0();
        __syncthreads();

        // warp fully masked for this k-tile? (keys all beyond last row of warp)
        const bool active = (j*64 <= qb*128 + w*16 + 15);
        if (active) {
            const uint32_t KB = sb + stg*FSTG;
            const uint32_t VB = KB + FTILE;

            // ---- QK^T, fp16 accumulators ----
            uint32_t scH[8][2];
#pragma unroll
            for (int t = 0; t < 8; t++) { scH[t][0] = 0u; scH[t][1] = 0u; }

            const uint32_t bo = (uint32_t)(((quad>>1)*8 + qi)*144 + (quad&1)*16);
#pragma unroll
            for (int kd = 0; kd < 4; kd++) {
                uint32_t bK[4][4];
#pragma unroll
                for (int p = 0; p < 4; p++)
                    ldm_x4(bK[p], KB + bo + p*(16*144) + kd*32);
#pragma unroll
                for (int t = 0; t < 8; t++)
                    mma16816hh(scH[t], qA[kd], &bK[t>>1][(t&1)*2]);
            }

            // unpack to fp32 (scale already folded into q)
            float sc[8][4];
#pragma unroll
            for (int t = 0; t < 8; t++) {
                float2 u0 = __half22float2(*(__half2*)&scH[t][0]);
                float2 u1 = __half22float2(*(__half2*)&scH[t][1]);
                sc[t][0] = u0.x; sc[t][1] = u0.y;
                sc[t][2] = u1.x; sc[t][3] = u1.y;
            }

            // ---- causal mask (partial tiles only) ----
            if (j*64 + 63 > qb*128 + w*16) {
#pragma unroll
                for (int t = 0; t < 8; t++) {
                    const int colb = j*64 + t*8 + 2*tig;
#pragma unroll
                    for (int e = 0; e < 4; e++) {
                        const int col = colb + (e & 1);
                        const int row = row0 + ((e >= 2) ? 8 : 0);
                        if (col > row) sc[t][e] = -1e30f;
                    }
                }
            }

            // ---- online softmax (rows g and g+8) ----
            float rm0 = -1e30f, rm1 = -1e30f;
#pragma unroll
            for (int t = 0; t < 8; t++) {
                rm0 = fmaxf(rm0, fmaxf(sc[t][0], sc[t][1]));
                rm1 = fmaxf(rm1, fmaxf(sc[t][2], sc[t][3]));
            }
            rm0 = fmaxf(rm0, __shfl_xor_sync(0xffffffffu, rm0, 1));
            rm0 = fmaxf(rm0, __shfl_xor_sync(0xffffffffu, rm0, 2));
            rm1 = fmaxf(rm1, __shfl_xor_sync(0xffffffffu, rm1, 1));
            rm1 = fmaxf(rm1, __shfl_xor_sync(0xffffffffu, rm1, 2));
            const float mn0 = fmaxf(m0, rm0), mn1 = fmaxf(m1, rm1);
            const float a0 = fexp(m0 - mn0), a1 = fexp(m1 - mn1);
            float s0 = 0.f, s1 = 0.f;
#pragma unroll
            for (int t = 0; t < 8; t++) {
                sc[t][0] = fexp(sc[t][0] - mn0); sc[t][1] = fexp(sc[t][1] - mn0);
                sc[t][2] = fexp(sc[t][2] - mn1); sc[t][3] = fexp(sc[t][3] - mn1);
                s0 += sc[t][0] + sc[t][1];
                s1 += sc[t][2] + sc[t][3];
            }
            s0 += __shfl_xor_sync(0xffffffffu, s0, 1);
            s0 += __shfl_xor_sync(0xffffffffu, s0, 2);
            s1 += __shfl_xor_sync(0xffffffffu, s1, 1);
            s1 += __shfl_xor_sync(0xffffffffu, s1, 2);
            l0 = l0 * a0 + s0; l1 = l1 * a1 + s1;
            m0 = mn0; m1 = mn1;
#pragma unroll
            for (int t = 0; t < 8; t++) {
                o[t][0] *= a0; o[t][1] *= a0; o[t][2] *= a1; o[t][3] *= a1;
            }

            // ---- PV: P fp16, V via ldmatrix.trans, f32 acc ----
            const uint32_t vo = (uint32_t)(((quad&1)*8 + qi)*144 + (quad>>1)*16);
#pragma unroll
            for (int kk = 0; kk < 4; kk++) {
                const int t0 = 2*kk, t1 = 2*kk + 1;
                uint32_t ap[4];
                ap[0] = hpack(sc[t0][0], sc[t0][1]);
                ap[1] = hpack(sc[t0][2], sc[t0][3]);
                ap[2] = hpack(sc[t1][0], sc[t1][1]);
                ap[3] = hpack(sc[t1][2], sc[t1][3]);

                uint32_t bV[4][4];
#pragma unroll
                for (int dp = 0; dp < 4; dp++)
                    ldm_x4_t(bV[dp], VB + vo + kk*(16*144) + dp*32);
#pragma unroll
                for (int dt = 0; dt < 8; dt++)
                    mma16816h(o[dt], ap, &bV[dt>>1][(dt&1)*2]);
            }
        }
        __syncthreads();
    }

    // ---- epilogue: normalize, write single fp16 attn output ----
    const float inv0 = 1.0f / l0, inv1 = 1.0f / l1;
    const int b = bh >> 4, h = bh & 15;
    const int s0r = qb*128 + w*16 + g;
    const int s1r = s0r + 8;
#pragma unroll
    for (int t = 0; t < 8; t++) {
        const float x0 = o[t][0]*inv0, x1 = o[t][1]*inv0;
        const float y0 = o[t][2]*inv1, y1 = o[t][3]*inv1;
        const int col = h*64 + t*8 + 2*tig;
        *(uint32_t*)(g_ah16 + ((size_t)(b*PS + s0r))*PD + col) = hpack(x0, x1);
        *(uint32_t*)(g_ah16 + ((size_t)(b*PS + s1r))*PD + col) = hpack(y0, y1);
    }
}

// ---------------------------------------------------------------------------
extern "C" void kernel_launch(void* const* d_in, const int* in_sizes, int n_in,
                              void* d_out, int out_size) {
    const float* x     = (const float*)d_in[0];
    const float* W_qkv = (const float*)d_in[1];
    const float* W_o   = (const float*)d_in[2];
    const int*   tpos  = (const int*)d_in[3];
    float* out = (float*)d_out;

    cudaFuncSetAttribute(flash_mma_kernel,
                         cudaFuncAttributeMaxDynamicSharedMemorySize, FLASH_SMEM);
    cudaFuncSetAttribute(mma_gemm_kernel<0>,
                         cudaFuncAttributeMaxDynamicSharedMemorySize, GEMM_SMEM);
    cudaFuncSetAttribute(mma_gemm_kernel<1>,
                         cudaFuncAttributeMaxDynamicSharedMemorySize, GEMM_SMEM);

    prep_kernel<<<(PREP_N + 255) / 256, 256>>>(x, W_qkv, W_o, tpos);

    mma_gemm_kernel<0><<<dim3(24, 64), 256, GEMM_SMEM>>>(nullptr);   // QKV + RoPE
    flash_mma_kernel<<<dim3(16, 64), 256, FLASH_SMEM>>>();
    mma_gemm_kernel<1><<<dim3(8, 64), 256, GEMM_SMEM>>>(out);        // out proj
}